// round 11
// baseline (speedup 1.0000x reference)
#include <cuda_runtime.h>
#include <cuda_bf16.h>
#include <cuda_fp16.h>
#include <math.h>
#include <stdint.h>

#define S_LEN 2048
#define DM    1024
#define NH    16
#define DK    64
#define SCALE 0.125f
#define EPSN  1e-6f

typedef __nv_bfloat16 bf16;

// ---------------- scratch (__device__ globals; allocation-free) ----------------
__device__ bf16   b_Qin[(size_t)S_LEN * DM];
__device__ bf16   b_Kin[(size_t)S_LEN * DM];
__device__ __half h_Vin[(size_t)S_LEN * DM];       // V input, single fp16
__device__ bf16   b_Wq[(size_t)DM * DM];
__device__ bf16   b_Wk[(size_t)DM * DM];
__device__ __half h_Wv_h[(size_t)DM * DM];         // W_v split fp16 hi/lo
__device__ __half h_Wv_l[(size_t)DM * DM];
__device__ __half h_Wo[(size_t)DM * DM];           // W_o single fp16

__device__ bf16   b_Qn[(size_t)NH * S_LEN * DK];   // normalized Q, [h][s][64]
__device__ bf16   b_Kn[(size_t)NH * S_LEN * DK];
__device__ __half v_Vt[(size_t)NH * DK * S_LEN];   // V^T fp16, [h][64][2048]

__device__ __half v_att[(size_t)S_LEN * DM];       // attended, single fp16

// ---------------- helpers ----------------
__device__ __forceinline__ uint32_t cvta_s(const void* p) {
    return (uint32_t)__cvta_generic_to_shared(p);
}
__device__ __forceinline__ void cp16(void* s, const void* g) {
    asm volatile("cp.async.cg.shared.global [%0],[%1],16;" ::
                 "r"(cvta_s(s)), "l"(g));
}
__device__ __forceinline__ void cp_commit() {
    asm volatile("cp.async.commit_group;");
}
template<int N>
__device__ __forceinline__ void cp_wait() {
    asm volatile("cp.async.wait_group %0;" :: "n"(N));
}
__device__ __forceinline__ void ldm4(uint32_t& r0, uint32_t& r1, uint32_t& r2, uint32_t& r3,
                                     uint32_t a) {
    asm volatile("ldmatrix.sync.aligned.m8n8.x4.shared.b16 {%0,%1,%2,%3},[%4];"
                 : "=r"(r0), "=r"(r1), "=r"(r2), "=r"(r3) : "r"(a));
}
__device__ __forceinline__ void ldm4t(uint32_t& r0, uint32_t& r1, uint32_t& r2, uint32_t& r3,
                                      uint32_t a) {
    asm volatile("ldmatrix.sync.aligned.m8n8.x4.trans.shared.b16 {%0,%1,%2,%3},[%4];"
                 : "=r"(r0), "=r"(r1), "=r"(r2), "=r"(r3) : "r"(a));
}
__device__ __forceinline__ void mma_bf(float c[4], const uint32_t a[4],
                                       uint32_t b0, uint32_t b1) {
    asm volatile(
        "mma.sync.aligned.m16n8k16.row.col.f32.bf16.bf16.f32 "
        "{%0,%1,%2,%3},{%4,%5,%6,%7},{%8,%9},{%0,%1,%2,%3};"
        : "+f"(c[0]), "+f"(c[1]), "+f"(c[2]), "+f"(c[3])
        : "r"(a[0]), "r"(a[1]), "r"(a[2]), "r"(a[3]), "r"(b0), "r"(b1));
}
__device__ __forceinline__ void mma_hf(float c[4], const uint32_t a[4],
                                       uint32_t b0, uint32_t b1) {
    asm volatile(
        "mma.sync.aligned.m16n8k16.row.col.f32.f16.f16.f32 "
        "{%0,%1,%2,%3},{%4,%5,%6,%7},{%8,%9},{%0,%1,%2,%3};"
        : "+f"(c[0]), "+f"(c[1]), "+f"(c[2]), "+f"(c[3])
        : "r"(a[0]), "r"(a[1]), "r"(a[2]), "r"(a[3]), "r"(b0), "r"(b1));
}
// pack two fp32 -> bf16x2 / f16x2; first arg in low 16 bits
__device__ __forceinline__ uint32_t packbf(float lo, float hi) {
    uint32_t r;
    asm("cvt.rn.bf16x2.f32 %0,%1,%2;" : "=r"(r) : "f"(hi), "f"(lo));
    return r;
}
__device__ __forceinline__ uint32_t packhf(float lo, float hi) {
    uint32_t r;
    asm("cvt.rn.f16x2.f32 %0,%1,%2;" : "=r"(r) : "f"(hi), "f"(lo));
    return r;
}
__device__ __forceinline__ float rhf(float x) {
    return __half2float(__float2half(x));
}

// ---------------- fused conversions (one launch) ----------------
__device__ __forceinline__ void cvt1(const float4* x, uint32_t* y, int i) {
    float4 v = x[i];
    y[2 * i + 0] = packbf(v.x, v.y);
    y[2 * i + 1] = packbf(v.z, v.w);
}
__device__ __forceinline__ void cvt1h(const float4* x, uint32_t* y, int i) {
    float4 v = x[i];
    y[2 * i + 0] = packhf(v.x, v.y);
    y[2 * i + 1] = packhf(v.z, v.w);
}
__device__ __forceinline__ void split1h(const float4* x, uint32_t* hi, uint32_t* lo, int i) {
    float4 v = x[i];
    float hx = rhf(v.x), hy = rhf(v.y), hz = rhf(v.z), hw = rhf(v.w);
    hi[2 * i + 0] = packhf(hx, hy);
    hi[2 * i + 1] = packhf(hz, hw);
    lo[2 * i + 0] = packhf(v.x - hx, v.y - hy);
    lo[2 * i + 1] = packhf(v.z - hz, v.w - hw);
}
__global__ void prep_all(const float4* Qin, const float4* Kin, const float4* Vin,
                         const float4* Wq, const float4* Wk, const float4* Wv,
                         const float4* Wo)
{
    const int NI = S_LEN * DM / 4;
    const int NW = DM * DM / 4;
    int i = blockIdx.x * 256 + threadIdx.x;
    if (i < NI) { cvt1(Qin, (uint32_t*)b_Qin, i); return; }
    i -= NI;
    if (i < NI) { cvt1(Kin, (uint32_t*)b_Kin, i); return; }
    i -= NI;
    if (i < NI) { cvt1h(Vin, (uint32_t*)h_Vin, i); return; }
    i -= NI;
    if (i < NW) { cvt1(Wq, (uint32_t*)b_Wq, i); return; }
    i -= NW;
    if (i < NW) { cvt1(Wk, (uint32_t*)b_Wk, i); return; }
    i -= NW;
    if (i < NW) { split1h(Wv, (uint32_t*)h_Wv_h, (uint32_t*)h_Wv_l, i); return; }
    i -= NW;
    cvt1h(Wo, (uint32_t*)h_Wo, i);
}

// ---------------- fused QKV projection GEMM (one launch, z selects role) ----------------
// z==0: V = Vin(f16) @ (Wv_h + Wv_l)(f16), 2-term -> transpose fp16 emit to v_Vt
//       (heavy role scheduled FIRST: lowest block ids)
// z==1: Q = Qin@Wq (bf16 1-term) -> L2-norm bf16 emit to b_Qn
// z==2: K = Kin@Wk (bf16 1-term) -> L2-norm bf16 emit to b_Kn
#define GSTG (128 * 40 + 2 * 32 * 136)   // elems/stage: A + Bh + Bl = 13824

__global__ void __launch_bounds__(256, 2)
qkv_gemm()
{
    extern __shared__ bf16 sm_[];
    const int z = blockIdx.z;
    const bool vrole = (z == 0);
    const char* Ap = vrole ? (const char*)h_Vin : (z == 1) ? (const char*)b_Qin
                                                           : (const char*)b_Kin;
    const char* Bp = vrole ? (const char*)h_Wv_h : (z == 1) ? (const char*)b_Wq
                                                            : (const char*)b_Wk;

    const int tid = threadIdx.x;
    const int w = tid >> 5, l = tid & 31;
    const int wm = (w >> 2) * 64, wn = (w & 3) * 32;
    const int row0 = blockIdx.y * 128, col0 = blockIdx.x * 128;
    const int NT = DM / 32;

    auto issue = [&](int it, int stg) {
        bf16* dA  = sm_ + stg * GSTG;
        bf16* dBh = dA + 128 * 40;
        bf16* dBl = dBh + 32 * 136;
        int k0 = it * 32;
        #pragma unroll
        for (int i = 0; i < 2; i++) {
            int pos = tid + i * 256;
            int r = pos >> 2, c = (pos & 3) * 8;
            cp16(dA + r * 40 + c, Ap + ((size_t)(row0 + r) * DM + k0 + c) * 2);
        }
        #pragma unroll
        for (int i = 0; i < 2; i++) {
            int pos = tid + i * 256;
            int r = pos >> 4, c = (pos & 15) * 8;
            cp16(dBh + r * 136 + c, Bp + ((size_t)(k0 + r) * DM + col0 + c) * 2);
            if (vrole)
                cp16(dBl + r * 136 + c, h_Wv_l + (size_t)(k0 + r) * DM + col0 + c);
        }
        cp_commit();
    };

    float acc[4][4][4];
    #pragma unroll
    for (int a = 0; a < 4; a++)
        #pragma unroll
        for (int b = 0; b < 4; b++)
            #pragma unroll
            for (int c = 0; c < 4; c++) acc[a][b][c] = 0.f;

    issue(0, 0);

    for (int it = 0; it < NT; it++) {
        cp_wait<0>();
        __syncthreads();
        if (it + 1 < NT) issue(it + 1, (it + 1) & 1);

        bf16* sA  = sm_ + (it & 1) * GSTG;
        bf16* sBh = sA + 128 * 40;
        bf16* sBl = sBh + 32 * 136;

        #pragma unroll
        for (int kc = 0; kc < 2; kc++) {
            uint32_t af[4][4], bfh[2][4];
            #pragma unroll
            for (int mt = 0; mt < 4; mt++)
                ldm4(af[mt][0], af[mt][1], af[mt][2], af[mt][3],
                     cvta_s(sA + (wm + mt * 16 + (l & 15)) * 40 + kc * 16 + ((l >> 4) * 8)));
            #pragma unroll
            for (int np = 0; np < 2; np++)
                ldm4t(bfh[np][0], bfh[np][1], bfh[np][2], bfh[np][3],
                      cvta_s(sBh + (kc * 16 + (l & 15)) * 136 + wn + np * 16 + ((l >> 4) * 8)));
            if (!vrole) {
                #pragma unroll
                for (int mt = 0; mt < 4; mt++)
                    #pragma unroll
                    for (int nt = 0; nt < 4; nt++)
                        mma_bf(acc[mt][nt], af[mt],
                               bfh[nt >> 1][(nt & 1) * 2], bfh[nt >> 1][(nt & 1) * 2 + 1]);
            } else {
                uint32_t bfl[2][4];
                #pragma unroll
                for (int np = 0; np < 2; np++)
                    ldm4t(bfl[np][0], bfl[np][1], bfl[np][2], bfl[np][3],
                          cvta_s(sBl + (kc * 16 + (l & 15)) * 136 + wn + np * 16 + ((l >> 4) * 8)));
                #pragma unroll
                for (int mt = 0; mt < 4; mt++)
                    #pragma unroll
                    for (int nt = 0; nt < 4; nt++) {
                        mma_hf(acc[mt][nt], af[mt],
                               bfh[nt >> 1][(nt & 1) * 2], bfh[nt >> 1][(nt & 1) * 2 + 1]);
                        mma_hf(acc[mt][nt], af[mt],
                               bfl[nt >> 1][(nt & 1) * 2], bfl[nt >> 1][(nt & 1) * 2 + 1]);
                    }
            }
        }
    }
    __syncthreads();   // protect smem reuse in epilogues

    if (!vrole) {
        // fused L2 norm over d (two 64-wide heads inside this 128-col tile)
        float* sq = (float*)sm_;                 // 128 rows x 16 (2 heads x 8 partials)
        const int cw = w & 3;
        const int hl = cw >> 1;
        const int slot = (cw & 1) * 4 + (l & 3);
        #pragma unroll
        for (int mt = 0; mt < 4; mt++) {
            float p0 = 0.f, p1 = 0.f;
            #pragma unroll
            for (int nt = 0; nt < 4; nt++) {
                p0 += acc[mt][nt][0] * acc[mt][nt][0] + acc[mt][nt][1] * acc[mt][nt][1];
                p1 += acc[mt][nt][2] * acc[mt][nt][2] + acc[mt][nt][3] * acc[mt][nt][3];
            }
            int rl = wm + mt * 16 + (l >> 2);
            sq[rl * 16 + hl * 8 + slot] = p0;
            sq[(rl + 8) * 16 + hl * 8 + slot] = p1;
        }
        __syncthreads();

        bf16* dst = (z == 1) ? b_Qn : b_Kn;
        const int hg = (col0 >> 6) + hl;
        #pragma unroll
        for (int mt = 0; mt < 4; mt++) {
            int rl = wm + mt * 16 + (l >> 2);
            float ss0 = 0.f, ss1 = 0.f;
            #pragma unroll
            for (int s = 0; s < 8; s++) {
                ss0 += sq[rl * 16 + hl * 8 + s];
                ss1 += sq[(rl + 8) * 16 + hl * 8 + s];
            }
            float inv0 = 1.0f / (sqrtf(ss0) + EPSN);
            float inv1 = 1.0f / (sqrtf(ss1) + EPSN);
            #pragma unroll
            for (int nt = 0; nt < 4; nt++) {
                int d = (wn & 63) + nt * 8 + (l & 3) * 2;
                ((uint32_t*)dst)[((size_t)hg * S_LEN + row0 + rl) * 32 + (d >> 1)] =
                    packbf(acc[mt][nt][0] * inv0, acc[mt][nt][1] * inv0);
                ((uint32_t*)dst)[((size_t)hg * S_LEN + row0 + rl + 8) * 32 + (d >> 1)] =
                    packbf(acc[mt][nt][2] * inv1, acc[mt][nt][3] * inv1);
            }
        }
    } else {
        // transpose, emit v_Vt (single fp16) [h][d][s]
        __half* sh = (__half*)sm_;
        #pragma unroll
        for (int mt = 0; mt < 4; mt++) {
            int rl = wm + mt * 16 + (l >> 2);
            #pragma unroll
            for (int nt = 0; nt < 4; nt++) {
                int c0 = wn + nt * 8 + (l & 3) * 2;
                #pragma unroll
                for (int j = 0; j < 2; j++) {
                    sh[(c0 + j) * 136 + rl]     = __float2half(acc[mt][nt][j]);
                    sh[(c0 + j) * 136 + rl + 8] = __float2half(acc[mt][nt][2 + j]);
                }
            }
        }
        __syncthreads();
        int cl = tid >> 1, soff = (tid & 1) * 64;
        int hg = (col0 + cl) >> 6, d = (col0 + cl) & 63;
        size_t gbase = ((size_t)hg * DK + d) * S_LEN + row0 + soff;
        const uint4* srch = (const uint4*)(sh + cl * 136 + soff);
        uint4* gh = (uint4*)(v_Vt + gbase);
        #pragma unroll
        for (int i = 0; i < 8; i++) gh[i] = srch[i];
    }
}

// ---------------- out GEMM: 128x64 tiles, SINGLE-term fp16 ----------------
#define OSTG (128 * 40 + 32 * 72)    // elems/stage: A + B = 7424

__global__ void __launch_bounds__(256, 2)
out_gemm(float* __restrict__ out)
{
    extern __shared__ __half smh_[];

    const int tid = threadIdx.x;
    const int w = tid >> 5, l = tid & 31;
    const int wm = (w & 3) * 32, wn = (w >> 2) * 32;     // 4 M-warps x 2 N-warps
    const int row0 = blockIdx.y * 128, col0 = blockIdx.x * 64;
    const int NT = DM / 32;

    auto issue = [&](int it, int stg) {
        __half* dA = smh_ + stg * OSTG;
        __half* dB = dA + 128 * 40;
        int k0 = it * 32;
        #pragma unroll
        for (int i = 0; i < 2; i++) {
            int pos = tid + i * 256;
            int r = pos >> 2, c = (pos & 3) * 8;
            cp16(dA + r * 40 + c, v_att + (size_t)(row0 + r) * DM + k0 + c);
        }
        {
            int r = tid >> 3, c = (tid & 7) * 8;
            cp16(dB + r * 72 + c, h_Wo + (size_t)(k0 + r) * DM + col0 + c);
        }
        cp_commit();
    };

    float acc[2][4][4];
    #pragma unroll
    for (int a = 0; a < 2; a++)
        #pragma unroll
        for (int b = 0; b < 4; b++)
            #pragma unroll
            for (int c = 0; c < 4; c++) acc[a][b][c] = 0.f;

    issue(0, 0);

    for (int it = 0; it < NT; it++) {
        cp_wait<0>();
        __syncthreads();
        if (it + 1 < NT) issue(it + 1, (it + 1) & 1);

        __half* sA = smh_ + (it & 1) * OSTG;
        __half* sB = sA + 128 * 40;

        #pragma unroll
        for (int kc = 0; kc < 2; kc++) {
            uint32_t af[2][4], bh[2][4];
            #pragma unroll
            for (int mt = 0; mt < 2; mt++)
                ldm4(af[mt][0], af[mt][1], af[mt][2], af[mt][3],
                     cvta_s(sA + (wm + mt * 16 + (l & 15)) * 40 + kc * 16 + ((l >> 4) * 8)));
            #pragma unroll
            for (int np = 0; np < 2; np++)
                ldm4t(bh[np][0], bh[np][1], bh[np][2], bh[np][3],
                      cvta_s(sB + (kc * 16 + (l & 15)) * 72 + wn + np * 16 + ((l >> 4) * 8)));
            #pragma unroll
            for (int mt = 0; mt < 2; mt++)
                #pragma unroll
                for (int nt = 0; nt < 4; nt++)
                    mma_hf(acc[mt][nt], af[mt],
                           bh[nt >> 1][(nt & 1) * 2], bh[nt >> 1][(nt & 1) * 2 + 1]);
        }
    }

    #pragma unroll
    for (int mt = 0; mt < 2; mt++) {
        int r = row0 + wm + mt * 16 + (l >> 2);
        #pragma unroll
        for (int nt = 0; nt < 4; nt++) {
            int c = col0 + wn + nt * 8 + (l & 3) * 2;
            *(float2*)&out[(size_t)r * DM + c] =
                make_float2(acc[mt][nt][0], acc[mt][nt][1]);
            *(float2*)&out[(size_t)(r + 8) * DM + c] =
                make_float2(acc[mt][nt][2], acc[mt][nt][3]);
        }
    }
}

// ---------------- fused attention: q-block 64, 128 threads, 3-stage, 4 CTAs/SM ----------------
#define ASTG (2 * 64 * 72)   // per-stage elems (K bf16 + V f16) = 9216

__global__ void __launch_bounds__(128, 4) attn_mma(const float* __restrict__ bias)
{
    extern __shared__ bf16 sm_[];

    const int tid = threadIdx.x, w = tid >> 5, l = tid & 31;
    const int h = blockIdx.y, qb = blockIdx.x * 64;

    // stage Q tile (64x64) through stage-0 area, grab fragments
    #pragma unroll
    for (int i = 0; i < 4; i++) {
        int pos = tid + i * 128;
        int r = pos >> 3, c = (pos & 7) * 8;
        *(uint4*)(sm_ + r * 72 + c) =
            *(const uint4*)(b_Qn + ((size_t)h * S_LEN + qb + r) * DK + c);
    }
    __syncthreads();
    uint32_t qf[4][4];
    #pragma unroll
    for (int dc = 0; dc < 4; dc++)
        ldm4(qf[dc][0], qf[dc][1], qf[dc][2], qf[dc][3],
             cvta_s(sm_ + (w * 16 + (l & 15)) * 72 + dc * 16 + ((l >> 4) * 8)));
    __syncthreads();

    auto issue = [&](int it, int stg) {
        bf16*   dK = sm_ + stg * ASTG;
        __half* dV = (__half*)(dK + 64 * 72);
        int kb = it * 64;
        #pragma unroll
        for (int i = 0; i < 4; i++) {
            int pos = tid + i * 128;
            int r = pos >> 3, c = (pos & 7) * 8;
            cp16(dK + r * 72 + c, b_Kn + ((size_t)h * S_LEN + kb + r) * DK + c);
            cp16(dV + r * 72 + c, v_Vt + ((size_t)h * DK + r) * S_LEN + kb + c);
        }
        cp_commit();
    };

    float oacc[8][4];
    #pragma unroll
    for (int a = 0; a < 8; a++)
        #pragma unroll
        for (int b = 0; b < 4; b++) oacc[a][b] = 0.f;
    float rs_lo = 0.f, rs_hi = 0.f;

    const float* bp = bias + ((size_t)h * S_LEN + qb + w * 16 + (l >> 2)) * S_LEN + (l & 3) * 2;

    issue(0, 0);
    issue(1, 1);

    const int NT = S_LEN / 64;
    for (int it = 0; it < NT; it++) {
        const int kb = it * 64;
        cp_wait<1>();
        __syncthreads();
        if (it + 2 < NT) issue(it + 2, (it + 2) % 3);

        bf16*   sK = sm_ + (it % 3) * ASTG;
        __half* sV = (__half*)(sK + 64 * 72);

        // prefetch bias for this tile (hides under the S mma below)
        float2 bv0[8], bv1[8];
        #pragma unroll
        for (int nt = 0; nt < 8; nt++) {
            bv0[nt] = *(const float2*)(bp + kb + nt * 8);
            bv1[nt] = *(const float2*)(bp + kb + nt * 8 + 8 * S_LEN);
        }

        // S = Q @ K^T (64 x 64 per block, 16 x 64 per warp)
        float s[8][4];
        #pragma unroll
        for (int a = 0; a < 8; a++)
            #pragma unroll
            for (int b = 0; b < 4; b++) s[a][b] = 0.f;
        #pragma unroll
        for (int dc = 0; dc < 4; dc++) {
            #pragma unroll
            for (int np = 0; np < 4; np++) {
                uint32_t r0, r1, r2, r3;
                ldm4(r0, r1, r2, r3,
                     cvta_s(sK + (np * 16 + (l & 15)) * 72 + dc * 16 + ((l >> 4) * 8)));
                mma_bf(s[2 * np],     qf[dc], r0, r2);
                mma_bf(s[2 * np + 1], qf[dc], r1, r3);
            }
        }

        // p = exp(s*SCALE + bias); row sums
        #pragma unroll
        for (int nt = 0; nt < 8; nt++) {
            float p0 = __expf(fmaf(s[nt][0], SCALE, bv0[nt].x));
            float p1 = __expf(fmaf(s[nt][1], SCALE, bv0[nt].y));
            float p2 = __expf(fmaf(s[nt][2], SCALE, bv1[nt].x));
            float p3 = __expf(fmaf(s[nt][3], SCALE, bv1[nt].y));
            rs_lo += p0 + p1;  rs_hi += p2 + p3;
            s[nt][0] = p0; s[nt][1] = p1; s[nt][2] = p2; s[nt][3] = p3;
        }

        // O += P @ V  (single fp16 each)
        #pragma unroll
        for (int kt = 0; kt < 4; kt++) {
            uint32_t a[4];
            a[0] = packhf(s[2 * kt][0],     s[2 * kt][1]);
            a[1] = packhf(s[2 * kt][2],     s[2 * kt][3]);
            a[2] = packhf(s[2 * kt + 1][0], s[2 * kt + 1][1]);
            a[3] = packhf(s[2 * kt + 1][2], s[2 * kt + 1][3]);
            #pragma unroll
            for (int dp = 0; dp < 4; dp++) {
                uint32_t v0, v1, v2, v3;
                ldm4(v0, v1, v2, v3,
                     cvta_s(sV + (dp * 16 + (l & 15)) * 72 + kt * 16 + ((l >> 4) * 8)));
                mma_hf(oacc[2 * dp],     a, v0, v2);
                mma_hf(oacc[2 * dp + 1], a, v1, v3);
            }
        }
    }

    // finalize: quad-reduce row sums, normalize, emit fp16 att
    rs_lo += __shfl_xor_sync(0xffffffffu, rs_lo, 1);
    rs_lo += __shfl_xor_sync(0xffffffffu, rs_lo, 2);
    rs_hi += __shfl_xor_sync(0xffffffffu, rs_hi, 1);
    rs_hi += __shfl_xor_sync(0xffffffffu, rs_hi, 2);
    float il = 1.0f / rs_lo, ih = 1.0f / rs_hi;

    #pragma unroll
    for (int nt = 0; nt < 8; nt++) {
        int r = qb + w * 16 + (l >> 2);
        int c = h * DK + nt * 8 + (l & 3) * 2;
        size_t i0 = ((size_t)r * DM + c) >> 1;
        size_t i1 = ((size_t)(r + 8) * DM + c) >> 1;
        ((uint32_t*)v_att)[i0] = packhf(oacc[nt][0] * il, oacc[nt][1] * il);
        ((uint32_t*)v_att)[i1] = packhf(oacc[nt][2] * ih, oacc[nt][3] * ih);
    }
}

// ---------------- launcher ----------------
extern "C" void kernel_launch(void* const* d_in, const int* in_sizes, int n_in,
                              void* d_out, int out_size)
{
    (void)in_sizes; (void)n_in; (void)out_size;
    const float* Qin  = (const float*)d_in[0];
    const float* Kin  = (const float*)d_in[1];
    const float* Vin  = (const float*)d_in[2];
    const float* bias = (const float*)d_in[3];
    const float* Wq   = (const float*)d_in[4];
    const float* Wk   = (const float*)d_in[5];
    const float* Wv   = (const float*)d_in[6];
    const float* Wo   = (const float*)d_in[7];
    float* out = (float*)d_out;

    const int NPREP = 3 * (S_LEN * DM / 4) + 4 * (DM * DM / 4);
    prep_all<<<NPREP / 256, 256>>>((const float4*)Qin, (const float4*)Kin,
                                   (const float4*)Vin, (const float4*)Wq,
                                   (const float4*)Wk, (const float4*)Wv,
                                   (const float4*)Wo);

    // fused QKV projections: z=0 V (heavy, scheduled first), z=1 Q, z=2 K
    const int smemG = 2 * GSTG * 2;                        // 55296 B
    cudaFuncSetAttribute(qkv_gemm,
                         cudaFuncAttributeMaxDynamicSharedMemorySize, smemG);
    qkv_gemm<<<dim3(DM / 128, S_LEN / 128, 3), 256, smemG>>>();

    const int smemA = 3 * ASTG * 2;                        // 55296 B
    cudaFuncSetAttribute(attn_mma,
                         cudaFuncAttributeMaxDynamicSharedMemorySize, smemA);
    attn_mma<<<dim3(S_LEN / 64, NH), 128, smemA>>>(bias);

    const int smemO = 2 * OSTG * 2;                        // 29696 B
    cudaFuncSetAttribute(out_gemm,
                         cudaFuncAttributeMaxDynamicSharedMemorySize, smemO);
    out_gemm<<<dim3(DM / 64, S_LEN / 128), 256, smemO>>>(out);
}

// round 13
// speedup vs baseline: 1.1260x; 1.1260x over previous
#include <cuda_runtime.h>
#include <cuda_bf16.h>
#include <cuda_fp16.h>
#include <math.h>
#include <stdint.h>

#define S_LEN 2048
#define DM    1024
#define NH    16
#define DK    64
#define SCALE 0.125f
#define EPSN  1e-6f

typedef __nv_bfloat16 bf16;

// ---------------- scratch (__device__ globals; allocation-free) ----------------
__device__ bf16   b_Qin[(size_t)S_LEN * DM];
__device__ bf16   b_Kin[(size_t)S_LEN * DM];
__device__ __half h_Vin[(size_t)S_LEN * DM];       // V input, single fp16
__device__ bf16   b_Wq[(size_t)DM * DM];
__device__ bf16   b_Wk[(size_t)DM * DM];
__device__ __half h_Wv_h[(size_t)DM * DM];         // W_v split fp16 hi/lo
__device__ __half h_Wv_l[(size_t)DM * DM];
__device__ __half h_Wo[(size_t)DM * DM];           // W_o single fp16

__device__ bf16   b_Qn[(size_t)NH * S_LEN * DK];   // normalized Q, [h][s][64]
__device__ bf16   b_Kn[(size_t)NH * S_LEN * DK];
__device__ __half v_Vt[(size_t)NH * DK * S_LEN];   // V^T fp16, [h][64][2048]

__device__ __half v_att[(size_t)S_LEN * DM];       // attended, single fp16

// ---------------- helpers ----------------
__device__ __forceinline__ uint32_t cvta_s(const void* p) {
    return (uint32_t)__cvta_generic_to_shared(p);
}
__device__ __forceinline__ void cp16(void* s, const void* g) {
    asm volatile("cp.async.cg.shared.global [%0],[%1],16;" ::
                 "r"(cvta_s(s)), "l"(g));
}
__device__ __forceinline__ void cp_commit() {
    asm volatile("cp.async.commit_group;");
}
template<int N>
__device__ __forceinline__ void cp_wait() {
    asm volatile("cp.async.wait_group %0;" :: "n"(N));
}
__device__ __forceinline__ void ldm4(uint32_t& r0, uint32_t& r1, uint32_t& r2, uint32_t& r3,
                                     uint32_t a) {
    asm volatile("ldmatrix.sync.aligned.m8n8.x4.shared.b16 {%0,%1,%2,%3},[%4];"
                 : "=r"(r0), "=r"(r1), "=r"(r2), "=r"(r3) : "r"(a));
}
__device__ __forceinline__ void ldm4t(uint32_t& r0, uint32_t& r1, uint32_t& r2, uint32_t& r3,
                                      uint32_t a) {
    asm volatile("ldmatrix.sync.aligned.m8n8.x4.trans.shared.b16 {%0,%1,%2,%3},[%4];"
                 : "=r"(r0), "=r"(r1), "=r"(r2), "=r"(r3) : "r"(a));
}
__device__ __forceinline__ void mma_bf(float c[4], const uint32_t a[4],
                                       uint32_t b0, uint32_t b1) {
    asm volatile(
        "mma.sync.aligned.m16n8k16.row.col.f32.bf16.bf16.f32 "
        "{%0,%1,%2,%3},{%4,%5,%6,%7},{%8,%9},{%0,%1,%2,%3};"
        : "+f"(c[0]), "+f"(c[1]), "+f"(c[2]), "+f"(c[3])
        : "r"(a[0]), "r"(a[1]), "r"(a[2]), "r"(a[3]), "r"(b0), "r"(b1));
}
__device__ __forceinline__ void mma_hf(float c[4], const uint32_t a[4],
                                       uint32_t b0, uint32_t b1) {
    asm volatile(
        "mma.sync.aligned.m16n8k16.row.col.f32.f16.f16.f32 "
        "{%0,%1,%2,%3},{%4,%5,%6,%7},{%8,%9},{%0,%1,%2,%3};"
        : "+f"(c[0]), "+f"(c[1]), "+f"(c[2]), "+f"(c[3])
        : "r"(a[0]), "r"(a[1]), "r"(a[2]), "r"(a[3]), "r"(b0), "r"(b1));
}
// pack two fp32 -> bf16x2 / f16x2; first arg in low 16 bits
__device__ __forceinline__ uint32_t packbf(float lo, float hi) {
    uint32_t r;
    asm("cvt.rn.bf16x2.f32 %0,%1,%2;" : "=r"(r) : "f"(hi), "f"(lo));
    return r;
}
__device__ __forceinline__ uint32_t packhf(float lo, float hi) {
    uint32_t r;
    asm("cvt.rn.f16x2.f32 %0,%1,%2;" : "=r"(r) : "f"(hi), "f"(lo));
    return r;
}
__device__ __forceinline__ float rhf(float x) {
    return __half2float(__float2half(x));
}

// ---------------- fused conversions (one launch) ----------------
__device__ __forceinline__ void cvt1(const float4* x, uint32_t* y, int i) {
    float4 v = x[i];
    y[2 * i + 0] = packbf(v.x, v.y);
    y[2 * i + 1] = packbf(v.z, v.w);
}
__device__ __forceinline__ void cvt1h(const float4* x, uint32_t* y, int i) {
    float4 v = x[i];
    y[2 * i + 0] = packhf(v.x, v.y);
    y[2 * i + 1] = packhf(v.z, v.w);
}
__device__ __forceinline__ void split1h(const float4* x, uint32_t* hi, uint32_t* lo, int i) {
    float4 v = x[i];
    float hx = rhf(v.x), hy = rhf(v.y), hz = rhf(v.z), hw = rhf(v.w);
    hi[2 * i + 0] = packhf(hx, hy);
    hi[2 * i + 1] = packhf(hz, hw);
    lo[2 * i + 0] = packhf(v.x - hx, v.y - hy);
    lo[2 * i + 1] = packhf(v.z - hz, v.w - hw);
}
__global__ void prep_all(const float4* Qin, const float4* Kin, const float4* Vin,
                         const float4* Wq, const float4* Wk, const float4* Wv,
                         const float4* Wo)
{
    const int NI = S_LEN * DM / 4;
    const int NW = DM * DM / 4;
    int i = blockIdx.x * 256 + threadIdx.x;
    if (i < NI) { cvt1(Qin, (uint32_t*)b_Qin, i); return; }
    i -= NI;
    if (i < NI) { cvt1(Kin, (uint32_t*)b_Kin, i); return; }
    i -= NI;
    if (i < NI) { cvt1h(Vin, (uint32_t*)h_Vin, i); return; }
    i -= NI;
    if (i < NW) { cvt1(Wq, (uint32_t*)b_Wq, i); return; }
    i -= NW;
    if (i < NW) { cvt1(Wk, (uint32_t*)b_Wk, i); return; }
    i -= NW;
    if (i < NW) { split1h(Wv, (uint32_t*)h_Wv_h, (uint32_t*)h_Wv_l, i); return; }
    i -= NW;
    cvt1h(Wo, (uint32_t*)h_Wo, i);
}

// ---------------- fused QKV projection GEMM (one launch, z selects role) ----------------
// z==0: V = Vin(f16) @ (Wv_h + Wv_l)(f16), 2-term -> transpose fp16 emit to v_Vt
// z==1: Q = Qin@Wq (bf16 1-term) -> L2-norm bf16 emit to b_Qn
// z==2: K = Kin@Wk (bf16 1-term) -> L2-norm bf16 emit to b_Kn
// 3-stage cp.async pipeline with graduated tail waits (race-free drain).
#define GSTG (128 * 40 + 2 * 32 * 136)   // elems/stage: A + Bh + Bl = 13824

__global__ void __launch_bounds__(256, 2)
qkv_gemm()
{
    extern __shared__ bf16 sm_[];
    const int z = blockIdx.z;
    const bool vrole = (z == 0);
    const char* Ap = vrole ? (const char*)h_Vin : (z == 1) ? (const char*)b_Qin
                                                           : (const char*)b_Kin;
    const char* Bp = vrole ? (const char*)h_Wv_h : (z == 1) ? (const char*)b_Wq
                                                            : (const char*)b_Wk;

    const int tid = threadIdx.x;
    const int w = tid >> 5, l = tid & 31;
    const int wm = (w >> 2) * 64, wn = (w & 3) * 32;
    const int row0 = blockIdx.y * 128, col0 = blockIdx.x * 128;
    const int NT = DM / 32;

    auto issue = [&](int it, int stg) {
        bf16* dA  = sm_ + stg * GSTG;
        bf16* dBh = dA + 128 * 40;
        bf16* dBl = dBh + 32 * 136;
        int k0 = it * 32;
        #pragma unroll
        for (int i = 0; i < 2; i++) {
            int pos = tid + i * 256;
            int r = pos >> 2, c = (pos & 3) * 8;
            cp16(dA + r * 40 + c, Ap + ((size_t)(row0 + r) * DM + k0 + c) * 2);
        }
        #pragma unroll
        for (int i = 0; i < 2; i++) {
            int pos = tid + i * 256;
            int r = pos >> 4, c = (pos & 15) * 8;
            cp16(dBh + r * 136 + c, Bp + ((size_t)(k0 + r) * DM + col0 + c) * 2);
            if (vrole)
                cp16(dBl + r * 136 + c, h_Wv_l + (size_t)(k0 + r) * DM + col0 + c);
        }
        cp_commit();
    };

    float acc[4][4][4];
    #pragma unroll
    for (int a = 0; a < 4; a++)
        #pragma unroll
        for (int b = 0; b < 4; b++)
            #pragma unroll
            for (int c = 0; c < 4; c++) acc[a][b][c] = 0.f;

    issue(0, 0);
    issue(1, 1);

    for (int it = 0; it < NT; it++) {
        // graduated tail wait: group `it` must be fully landed before reading
        if (it + 2 < NT) cp_wait<1>(); else cp_wait<0>();
        __syncthreads();
        if (it + 2 < NT) issue(it + 2, (it + 2) % 3);

        bf16* sA  = sm_ + (it % 3) * GSTG;
        bf16* sBh = sA + 128 * 40;
        bf16* sBl = sBh + 32 * 136;

        #pragma unroll
        for (int kc = 0; kc < 2; kc++) {
            uint32_t af[4][4], bfh[2][4];
            #pragma unroll
            for (int mt = 0; mt < 4; mt++)
                ldm4(af[mt][0], af[mt][1], af[mt][2], af[mt][3],
                     cvta_s(sA + (wm + mt * 16 + (l & 15)) * 40 + kc * 16 + ((l >> 4) * 8)));
            #pragma unroll
            for (int np = 0; np < 2; np++)
                ldm4t(bfh[np][0], bfh[np][1], bfh[np][2], bfh[np][3],
                      cvta_s(sBh + (kc * 16 + (l & 15)) * 136 + wn + np * 16 + ((l >> 4) * 8)));
            if (!vrole) {
                #pragma unroll
                for (int mt = 0; mt < 4; mt++)
                    #pragma unroll
                    for (int nt = 0; nt < 4; nt++)
                        mma_bf(acc[mt][nt], af[mt],
                               bfh[nt >> 1][(nt & 1) * 2], bfh[nt >> 1][(nt & 1) * 2 + 1]);
            } else {
                uint32_t bfl[2][4];
                #pragma unroll
                for (int np = 0; np < 2; np++)
                    ldm4t(bfl[np][0], bfl[np][1], bfl[np][2], bfl[np][3],
                          cvta_s(sBl + (kc * 16 + (l & 15)) * 136 + wn + np * 16 + ((l >> 4) * 8)));
                #pragma unroll
                for (int mt = 0; mt < 4; mt++)
                    #pragma unroll
                    for (int nt = 0; nt < 4; nt++) {
                        mma_hf(acc[mt][nt], af[mt],
                               bfh[nt >> 1][(nt & 1) * 2], bfh[nt >> 1][(nt & 1) * 2 + 1]);
                        mma_hf(acc[mt][nt], af[mt],
                               bfl[nt >> 1][(nt & 1) * 2], bfl[nt >> 1][(nt & 1) * 2 + 1]);
                    }
            }
        }
    }
    __syncthreads();   // protect smem reuse in epilogues

    if (!vrole) {
        // fused L2 norm over d (two 64-wide heads inside this 128-col tile)
        float* sq = (float*)sm_;                 // 128 rows x 16 (2 heads x 8 partials)
        const int cw = w & 3;
        const int hl = cw >> 1;
        const int slot = (cw & 1) * 4 + (l & 3);
        #pragma unroll
        for (int mt = 0; mt < 4; mt++) {
            float p0 = 0.f, p1 = 0.f;
            #pragma unroll
            for (int nt = 0; nt < 4; nt++) {
                p0 += acc[mt][nt][0] * acc[mt][nt][0] + acc[mt][nt][1] * acc[mt][nt][1];
                p1 += acc[mt][nt][2] * acc[mt][nt][2] + acc[mt][nt][3] * acc[mt][nt][3];
            }
            int rl = wm + mt * 16 + (l >> 2);
            sq[rl * 16 + hl * 8 + slot] = p0;
            sq[(rl + 8) * 16 + hl * 8 + slot] = p1;
        }
        __syncthreads();

        bf16* dst = (z == 1) ? b_Qn : b_Kn;
        const int hg = (col0 >> 6) + hl;
        #pragma unroll
        for (int mt = 0; mt < 4; mt++) {
            int rl = wm + mt * 16 + (l >> 2);
            float ss0 = 0.f, ss1 = 0.f;
            #pragma unroll
            for (int s = 0; s < 8; s++) {
                ss0 += sq[rl * 16 + hl * 8 + s];
                ss1 += sq[(rl + 8) * 16 + hl * 8 + s];
            }
            float inv0 = 1.0f / (sqrtf(ss0) + EPSN);
            float inv1 = 1.0f / (sqrtf(ss1) + EPSN);
            #pragma unroll
            for (int nt = 0; nt < 4; nt++) {
                int d = (wn & 63) + nt * 8 + (l & 3) * 2;
                ((uint32_t*)dst)[((size_t)hg * S_LEN + row0 + rl) * 32 + (d >> 1)] =
                    packbf(acc[mt][nt][0] * inv0, acc[mt][nt][1] * inv0);
                ((uint32_t*)dst)[((size_t)hg * S_LEN + row0 + rl + 8) * 32 + (d >> 1)] =
                    packbf(acc[mt][nt][2] * inv1, acc[mt][nt][3] * inv1);
            }
        }
    } else {
        // transpose, emit v_Vt (single fp16) [h][d][s]
        __half* sh = (__half*)sm_;
        #pragma unroll
        for (int mt = 0; mt < 4; mt++) {
            int rl = wm + mt * 16 + (l >> 2);
            #pragma unroll
            for (int nt = 0; nt < 4; nt++) {
                int c0 = wn + nt * 8 + (l & 3) * 2;
                #pragma unroll
                for (int j = 0; j < 2; j++) {
                    sh[(c0 + j) * 136 + rl]     = __float2half(acc[mt][nt][j]);
                    sh[(c0 + j) * 136 + rl + 8] = __float2half(acc[mt][nt][2 + j]);
                }
            }
        }
        __syncthreads();
        int cl = tid >> 1, soff = (tid & 1) * 64;
        int hg = (col0 + cl) >> 6, d = (col0 + cl) & 63;
        size_t gbase = ((size_t)hg * DK + d) * S_LEN + row0 + soff;
        const uint4* srch = (const uint4*)(sh + cl * 136 + soff);
        uint4* gh = (uint4*)(v_Vt + gbase);
        #pragma unroll
        for (int i = 0; i < 8; i++) gh[i] = srch[i];
    }
}

// ---------------- out GEMM: 128x64 tiles, 1-term fp16, 4-stage pipeline ----------------
#define OSTG (128 * 40 + 32 * 72)    // elems/stage: A + B = 7424

__global__ void __launch_bounds__(256, 2)
out_gemm(float* __restrict__ out)
{
    extern __shared__ __half smh_[];

    const int tid = threadIdx.x;
    const int w = tid >> 5, l = tid & 31;
    const int wm = (w & 3) * 32, wn = (w >> 2) * 32;     // 4 M-warps x 2 N-warps
    const int row0 = blockIdx.y * 128, col0 = blockIdx.x * 64;
    const int NT = DM / 32;

    auto issue = [&](int it, int stg) {
        __half* dA = smh_ + stg * OSTG;
        __half* dB = dA + 128 * 40;
        int k0 = it * 32;
        #pragma unroll
        for (int i = 0; i < 2; i++) {
            int pos = tid + i * 256;
            int r = pos >> 2, c = (pos & 3) * 8;
            cp16(dA + r * 40 + c, v_att + (size_t)(row0 + r) * DM + k0 + c);
        }
        {
            int r = tid >> 3, c = (tid & 7) * 8;
            cp16(dB + r * 72 + c, h_Wo + (size_t)(k0 + r) * DM + col0 + c);
        }
        cp_commit();
    };

    float acc[2][4][4];
    #pragma unroll
    for (int a = 0; a < 2; a++)
        #pragma unroll
        for (int b = 0; b < 4; b++)
            #pragma unroll
            for (int c = 0; c < 4; c++) acc[a][b][c] = 0.f;

    issue(0, 0);
    issue(1, 1);
    issue(2, 2);

    for (int it = 0; it < NT; it++) {
        if (it + 3 < NT) cp_wait<2>(); else cp_wait<0>();
        __syncthreads();
        if (it + 3 < NT) issue(it + 3, (it + 3) & 3);

        __half* sA = smh_ + (it & 3) * OSTG;
        __half* sB = sA + 128 * 40;

        #pragma unroll
        for (int kc = 0; kc < 2; kc++) {
            uint32_t af[2][4], bh[2][4];
            #pragma unroll
            for (int mt = 0; mt < 2; mt++)
                ldm4(af[mt][0], af[mt][1], af[mt][2], af[mt][3],
                     cvta_s(sA + (wm + mt * 16 + (l & 15)) * 40 + kc * 16 + ((l >> 4) * 8)));
            #pragma unroll
            for (int np = 0; np < 2; np++)
                ldm4t(bh[np][0], bh[np][1], bh[np][2], bh[np][3],
                      cvta_s(sB + (kc * 16 + (l & 15)) * 72 + wn + np * 16 + ((l >> 4) * 8)));
            #pragma unroll
            for (int mt = 0; mt < 2; mt++)
                #pragma unroll
                for (int nt = 0; nt < 4; nt++)
                    mma_hf(acc[mt][nt], af[mt],
                           bh[nt >> 1][(nt & 1) * 2], bh[nt >> 1][(nt & 1) * 2 + 1]);
        }
    }

    #pragma unroll
    for (int mt = 0; mt < 2; mt++) {
        int r = row0 + wm + mt * 16 + (l >> 2);
        #pragma unroll
        for (int nt = 0; nt < 4; nt++) {
            int c = col0 + wn + nt * 8 + (l & 3) * 2;
            *(float2*)&out[(size_t)r * DM + c] =
                make_float2(acc[mt][nt][0], acc[mt][nt][1]);
            *(float2*)&out[(size_t)(r + 8) * DM + c] =
                make_float2(acc[mt][nt][2], acc[mt][nt][3]);
        }
    }
}

// ---------------- fused attention: q-block 128, 256 thr, 4-stage, safe drain ----------------
#define ASTG (2 * 64 * 72)   // per-stage elems (K bf16 + V f16) = 9216

__global__ void __launch_bounds__(256, 2) attn_mma(const float* __restrict__ bias)
{
    extern __shared__ bf16 sm_[];

    const int tid = threadIdx.x, w = tid >> 5, l = tid & 31;
    const int h = blockIdx.y, qb = blockIdx.x * 128;

    // stage Q tile (128x64) through stage-0/1 area, grab fragments
    #pragma unroll
    for (int i = 0; i < 4; i++) {
        int pos = tid + i * 256;
        int r = pos >> 3, c = (pos & 7) * 8;
        *(uint4*)(sm_ + r * 72 + c) =
            *(const uint4*)(b_Qn + ((size_t)h * S_LEN + qb + r) * DK + c);
    }
    __syncthreads();
    uint32_t qf[4][4];
    #pragma unroll
    for (int dc = 0; dc < 4; dc++)
        ldm4(qf[dc][0], qf[dc][1], qf[dc][2], qf[dc][3],
             cvta_s(sm_ + (w * 16 + (l & 15)) * 72 + dc * 16 + ((l >> 4) * 8)));
    __syncthreads();

    auto issue = [&](int it, int stg) {
        bf16*   dK = sm_ + stg * ASTG;
        __half* dV = (__half*)(dK + 64 * 72);
        int kb = it * 64;
        #pragma unroll
        for (int i = 0; i < 2; i++) {
            int pos = tid + i * 256;
            int r = pos >> 3, c = (pos & 7) * 8;
            cp16(dK + r * 72 + c, b_Kn + ((size_t)h * S_LEN + kb + r) * DK + c);
            cp16(dV + r * 72 + c, v_Vt + ((size_t)h * DK + r) * S_LEN + kb + c);
        }
        cp_commit();
    };

    float oacc[8][4];
    #pragma unroll
    for (int a = 0; a < 8; a++)
        #pragma unroll
        for (int b = 0; b < 4; b++) oacc[a][b] = 0.f;
    float rs_lo = 0.f, rs_hi = 0.f;

    const float* bp = bias + ((size_t)h * S_LEN + qb + w * 16 + (l >> 2)) * S_LEN + (l & 3) * 2;

    issue(0, 0);
    issue(1, 1);
    issue(2, 2);

    const int NT = S_LEN / 64;
    for (int it = 0; it < NT; it++) {
        const int kb = it * 64;
        if (it + 3 < NT) cp_wait<2>(); else cp_wait<0>();
        __syncthreads();
        if (it + 3 < NT) issue(it + 3, (it + 3) & 3);

        bf16*   sK = sm_ + (it & 3) * ASTG;
        __half* sV = (__half*)(sK + 64 * 72);

        // prefetch bias for this tile (hides under the S mma below)
        float2 bv0[8], bv1[8];
        #pragma unroll
        for (int nt = 0; nt < 8; nt++) {
            bv0[nt] = *(const float2*)(bp + kb + nt * 8);
            bv1[nt] = *(const float2*)(bp + kb + nt * 8 + 8 * S_LEN);
        }

        // S = Q @ K^T (128 x 64 tile per block, 16 x 64 per warp)
        float s[8][4];
        #pragma unroll
        for (int a = 0; a < 8; a++)
            #pragma unroll
            for (int b = 0; b < 4; b++) s[a][b] = 0.f;
        #pragma unroll
        for (int dc = 0; dc < 4; dc++) {
            #pragma unroll
            for (int np = 0; np < 4; np++) {
                uint32_t r0, r1, r2, r3;
                ldm4(r0, r1, r2, r3,
                     cvta_s(sK + (np * 16 + (l & 15)) * 72 + dc * 16 + ((l >> 4) * 8)));
                mma_bf(s[2 * np],     qf[dc], r0, r2);
                mma_bf(s[2 * np + 1], qf[dc], r1, r3);
            }
        }

        // p = exp(s*SCALE + bias); row sums
        #pragma unroll
        for (int nt = 0; nt < 8; nt++) {
            float p0 = __expf(fmaf(s[nt][0], SCALE, bv0[nt].x));
            float p1 = __expf(fmaf(s[nt][1], SCALE, bv0[nt].y));
            float p2 = __expf(fmaf(s[nt][2], SCALE, bv1[nt].x));
            float p3 = __expf(fmaf(s[nt][3], SCALE, bv1[nt].y));
            rs_lo += p0 + p1;  rs_hi += p2 + p3;
            s[nt][0] = p0; s[nt][1] = p1; s[nt][2] = p2; s[nt][3] = p3;
        }

        // O += P @ V  (single fp16 each)
        #pragma unroll
        for (int kt = 0; kt < 4; kt++) {
            uint32_t a[4];
            a[0] = packhf(s[2 * kt][0],     s[2 * kt][1]);
            a[1] = packhf(s[2 * kt][2],     s[2 * kt][3]);
            a[2] = packhf(s[2 * kt + 1][0], s[2 * kt + 1][1]);
            a[3] = packhf(s[2 * kt + 1][2], s[2 * kt + 1][3]);
            #pragma unroll
            for (int dp = 0; dp < 4; dp++) {
                uint32_t v0, v1, v2, v3;
                ldm4(v0, v1, v2, v3,
                     cvta_s(sV + (dp * 16 + (l & 15)) * 72 + kt * 16 + ((l >> 4) * 8)));
                mma_hf(oacc[2 * dp],     a, v0, v2);
                mma_hf(oacc[2 * dp + 1], a, v1, v3);
            }
        }
    }

    // finalize: quad-reduce row sums, normalize, emit fp16 att
    rs_lo += __shfl_xor_sync(0xffffffffu, rs_lo, 1);
    rs_lo += __shfl_xor_sync(0xffffffffu, rs_lo, 2);
    rs_hi += __shfl_xor_sync(0xffffffffu, rs_hi, 1);
    rs_hi += __shfl_xor_sync(0xffffffffu, rs_hi, 2);
    float il = 1.0f / rs_lo, ih = 1.0f / rs_hi;

    #pragma unroll
    for (int nt = 0; nt < 8; nt++) {
        int r = qb + w * 16 + (l >> 2);
        int c = h * DK + nt * 8 + (l & 3) * 2;
        size_t i0 = ((size_t)r * DM + c) >> 1;
        size_t i1 = ((size_t)(r + 8) * DM + c) >> 1;
        ((uint32_t*)v_att)[i0] = packhf(oacc[nt][0] * il, oacc[nt][1] * il);
        ((uint32_t*)v_att)[i1] = packhf(oacc[nt][2] * ih, oacc[nt][3] * ih);
    }
}

// ---------------- launcher ----------------
extern "C" void kernel_launch(void* const* d_in, const int* in_sizes, int n_in,
                              void* d_out, int out_size)
{
    (void)in_sizes; (void)n_in; (void)out_size;
    const float* Qin  = (const float*)d_in[0];
    const float* Kin  = (const float*)d_in[1];
    const float* Vin  = (const float*)d_in[2];
    const float* bias = (const float*)d_in[3];
    const float* Wq   = (const float*)d_in[4];
    const float* Wk   = (const float*)d_in[5];
    const float* Wv   = (const float*)d_in[6];
    const float* Wo   = (const float*)d_in[7];
    float* out = (float*)d_out;

    const int NPREP = 3 * (S_LEN * DM / 4) + 4 * (DM * DM / 4);
    prep_all<<<NPREP / 256, 256>>>((const float4*)Qin, (const float4*)Kin,
                                   (const float4*)Vin, (const float4*)Wq,
                                   (const float4*)Wk, (const float4*)Wv,
                                   (const float4*)Wo);

    // fused QKV projections: z=0 V (heavy, scheduled first), z=1 Q, z=2 K
    const int smemG = 3 * GSTG * 2;                        // 82944 B
    cudaFuncSetAttribute(qkv_gemm,
                         cudaFuncAttributeMaxDynamicSharedMemorySize, smemG);
    qkv_gemm<<<dim3(DM / 128, S_LEN / 128, 3), 256, smemG>>>();

    const int smemA = 4 * ASTG * 2;                        // 73728 B
    cudaFuncSetAttribute(attn_mma,
                         cudaFuncAttributeMaxDynamicSharedMemorySize, smemA);
    attn_mma<<<dim3(S_LEN / 128, NH), 256, smemA>>>(bias);

    const int smemO = 4 * OSTG * 2;                        // 59392 B
    cudaFuncSetAttribute(out_gemm,
                         cudaFuncAttributeMaxDynamicSharedMemorySize, smemO);
    out_gemm<<<dim3(DM / 64, S_LEN / 128), 256, smemO>>>(out);
}

// round 14
// speedup vs baseline: 1.1927x; 1.0593x over previous
#include <cuda_runtime.h>
#include <cuda_bf16.h>
#include <cuda_fp16.h>
#include <math.h>
#include <stdint.h>

#define S_LEN 2048
#define DM    1024
#define NH    16
#define DK    64
#define SCALE 0.125f
#define EPSN  1e-6f

typedef __nv_bfloat16 bf16;

// ---------------- scratch (__device__ globals; allocation-free) ----------------
__device__ bf16   b_Qin[(size_t)S_LEN * DM];
__device__ bf16   b_Kin[(size_t)S_LEN * DM];
__device__ __half h_Vin[(size_t)S_LEN * DM];       // V input, single fp16
__device__ bf16   b_Wq[(size_t)DM * DM];
__device__ bf16   b_Wk[(size_t)DM * DM];
__device__ __half h_Wv[(size_t)DM * DM];           // W_v single fp16
__device__ __half h_Wo[(size_t)DM * DM];           // W_o single fp16

__device__ bf16   b_Qn[(size_t)NH * S_LEN * DK];   // normalized Q, [h][s][64]
__device__ bf16   b_Kn[(size_t)NH * S_LEN * DK];
__device__ __half v_Vt[(size_t)NH * DK * S_LEN];   // V^T fp16, [h][64][2048]

__device__ __half v_att[(size_t)S_LEN * DM];       // attended, single fp16

// ---------------- helpers ----------------
__device__ __forceinline__ uint32_t cvta_s(const void* p) {
    return (uint32_t)__cvta_generic_to_shared(p);
}
__device__ __forceinline__ void cp16(void* s, const void* g) {
    asm volatile("cp.async.cg.shared.global [%0],[%1],16;" ::
                 "r"(cvta_s(s)), "l"(g));
}
__device__ __forceinline__ void cp_commit() {
    asm volatile("cp.async.commit_group;");
}
template<int N>
__device__ __forceinline__ void cp_wait() {
    asm volatile("cp.async.wait_group %0;" :: "n"(N));
}
__device__ __forceinline__ void ldm4(uint32_t& r0, uint32_t& r1, uint32_t& r2, uint32_t& r3,
                                     uint32_t a) {
    asm volatile("ldmatrix.sync.aligned.m8n8.x4.shared.b16 {%0,%1,%2,%3},[%4];"
                 : "=r"(r0), "=r"(r1), "=r"(r2), "=r"(r3) : "r"(a));
}
__device__ __forceinline__ void ldm4t(uint32_t& r0, uint32_t& r1, uint32_t& r2, uint32_t& r3,
                                      uint32_t a) {
    asm volatile("ldmatrix.sync.aligned.m8n8.x4.trans.shared.b16 {%0,%1,%2,%3},[%4];"
                 : "=r"(r0), "=r"(r1), "=r"(r2), "=r"(r3) : "r"(a));
}
__device__ __forceinline__ void mma_bf(float c[4], const uint32_t a[4],
                                       uint32_t b0, uint32_t b1) {
    asm volatile(
        "mma.sync.aligned.m16n8k16.row.col.f32.bf16.bf16.f32 "
        "{%0,%1,%2,%3},{%4,%5,%6,%7},{%8,%9},{%0,%1,%2,%3};"
        : "+f"(c[0]), "+f"(c[1]), "+f"(c[2]), "+f"(c[3])
        : "r"(a[0]), "r"(a[1]), "r"(a[2]), "r"(a[3]), "r"(b0), "r"(b1));
}
__device__ __forceinline__ void mma_hf(float c[4], const uint32_t a[4],
                                       uint32_t b0, uint32_t b1) {
    asm volatile(
        "mma.sync.aligned.m16n8k16.row.col.f32.f16.f16.f32 "
        "{%0,%1,%2,%3},{%4,%5,%6,%7},{%8,%9},{%0,%1,%2,%3};"
        : "+f"(c[0]), "+f"(c[1]), "+f"(c[2]), "+f"(c[3])
        : "r"(a[0]), "r"(a[1]), "r"(a[2]), "r"(a[3]), "r"(b0), "r"(b1));
}
// pack two fp32 -> bf16x2 / f16x2; first arg in low 16 bits
__device__ __forceinline__ uint32_t packbf(float lo, float hi) {
    uint32_t r;
    asm("cvt.rn.bf16x2.f32 %0,%1,%2;" : "=r"(r) : "f"(hi), "f"(lo));
    return r;
}
__device__ __forceinline__ uint32_t packhf(float lo, float hi) {
    uint32_t r;
    asm("cvt.rn.f16x2.f32 %0,%1,%2;" : "=r"(r) : "f"(hi), "f"(lo));
    return r;
}

// ---------------- fused conversions (one launch) ----------------
__device__ __forceinline__ void cvt1(const float4* x, uint32_t* y, int i) {
    float4 v = x[i];
    y[2 * i + 0] = packbf(v.x, v.y);
    y[2 * i + 1] = packbf(v.z, v.w);
}
__device__ __forceinline__ void cvt1h(const float4* x, uint32_t* y, int i) {
    float4 v = x[i];
    y[2 * i + 0] = packhf(v.x, v.y);
    y[2 * i + 1] = packhf(v.z, v.w);
}
__global__ void prep_all(const float4* Qin, const float4* Kin, const float4* Vin,
                         const float4* Wq, const float4* Wk, const float4* Wv,
                         const float4* Wo)
{
    const int NI = S_LEN * DM / 4;
    const int NW = DM * DM / 4;
    int i = blockIdx.x * 256 + threadIdx.x;
    if (i < NI) { cvt1(Qin, (uint32_t*)b_Qin, i); return; }
    i -= NI;
    if (i < NI) { cvt1(Kin, (uint32_t*)b_Kin, i); return; }
    i -= NI;
    if (i < NI) { cvt1h(Vin, (uint32_t*)h_Vin, i); return; }
    i -= NI;
    if (i < NW) { cvt1(Wq, (uint32_t*)b_Wq, i); return; }
    i -= NW;
    if (i < NW) { cvt1(Wk, (uint32_t*)b_Wk, i); return; }
    i -= NW;
    if (i < NW) { cvt1h(Wv, (uint32_t*)h_Wv, i); return; }
    i -= NW;
    cvt1h(Wo, (uint32_t*)h_Wo, i);
}

// ---------------- fused QKV projection GEMM (uniform 1-term, z selects role) ----------------
// z==0: V = Vin(f16) @ Wv(f16) -> transpose fp16 emit to v_Vt
// z==1: Q = Qin@Wq (bf16)      -> L2-norm bf16 emit to b_Qn
// z==2: K = Kin@Wk (bf16)      -> L2-norm bf16 emit to b_Kn
// 3-stage cp.async pipeline with graduated tail waits.
#define GSTG (128 * 40 + 32 * 136)   // elems/stage: A + B = 9472

__global__ void __launch_bounds__(256, 2)
qkv_gemm()
{
    extern __shared__ bf16 sm_[];
    const int z = blockIdx.z;
    const bool vrole = (z == 0);
    const char* Ap = vrole ? (const char*)h_Vin : (z == 1) ? (const char*)b_Qin
                                                           : (const char*)b_Kin;
    const char* Bp = vrole ? (const char*)h_Wv : (z == 1) ? (const char*)b_Wq
                                                          : (const char*)b_Wk;

    const int tid = threadIdx.x;
    const int w = tid >> 5, l = tid & 31;
    const int wm = (w >> 2) * 64, wn = (w & 3) * 32;
    const int row0 = blockIdx.y * 128, col0 = blockIdx.x * 128;
    const int NT = DM / 32;

    auto issue = [&](int it, int stg) {
        bf16* dA = sm_ + stg * GSTG;
        bf16* dB = dA + 128 * 40;
        int k0 = it * 32;
        #pragma unroll
        for (int i = 0; i < 2; i++) {
            int pos = tid + i * 256;
            int r = pos >> 2, c = (pos & 3) * 8;
            cp16(dA + r * 40 + c, Ap + ((size_t)(row0 + r) * DM + k0 + c) * 2);
        }
        #pragma unroll
        for (int i = 0; i < 2; i++) {
            int pos = tid + i * 256;
            int r = pos >> 4, c = (pos & 15) * 8;
            cp16(dB + r * 136 + c, Bp + ((size_t)(k0 + r) * DM + col0 + c) * 2);
        }
        cp_commit();
    };

    float acc[4][4][4];
    #pragma unroll
    for (int a = 0; a < 4; a++)
        #pragma unroll
        for (int b = 0; b < 4; b++)
            #pragma unroll
            for (int c = 0; c < 4; c++) acc[a][b][c] = 0.f;

    issue(0, 0);
    issue(1, 1);

    for (int it = 0; it < NT; it++) {
        if (it + 2 < NT) cp_wait<1>(); else cp_wait<0>();
        __syncthreads();
        if (it + 2 < NT) issue(it + 2, (it + 2) % 3);

        bf16* sA = sm_ + (it % 3) * GSTG;
        bf16* sB = sA + 128 * 40;

        #pragma unroll
        for (int kc = 0; kc < 2; kc++) {
            uint32_t af[4][4], bfh[2][4];
            #pragma unroll
            for (int mt = 0; mt < 4; mt++)
                ldm4(af[mt][0], af[mt][1], af[mt][2], af[mt][3],
                     cvta_s(sA + (wm + mt * 16 + (l & 15)) * 40 + kc * 16 + ((l >> 4) * 8)));
            #pragma unroll
            for (int np = 0; np < 2; np++)
                ldm4t(bfh[np][0], bfh[np][1], bfh[np][2], bfh[np][3],
                      cvta_s(sB + (kc * 16 + (l & 15)) * 136 + wn + np * 16 + ((l >> 4) * 8)));
            if (!vrole) {
                #pragma unroll
                for (int mt = 0; mt < 4; mt++)
                    #pragma unroll
                    for (int nt = 0; nt < 4; nt++)
                        mma_bf(acc[mt][nt], af[mt],
                               bfh[nt >> 1][(nt & 1) * 2], bfh[nt >> 1][(nt & 1) * 2 + 1]);
            } else {
                #pragma unroll
                for (int mt = 0; mt < 4; mt++)
                    #pragma unroll
                    for (int nt = 0; nt < 4; nt++)
                        mma_hf(acc[mt][nt], af[mt],
                               bfh[nt >> 1][(nt & 1) * 2], bfh[nt >> 1][(nt & 1) * 2 + 1]);
            }
        }
    }
    __syncthreads();   // protect smem reuse in epilogues

    if (!vrole) {
        // fused L2 norm over d (two 64-wide heads inside this 128-col tile)
        float* sq = (float*)sm_;                 // 128 rows x 16 (2 heads x 8 partials)
        const int cw = w & 3;
        const int hl = cw >> 1;
        const int slot = (cw & 1) * 4 + (l & 3);
        #pragma unroll
        for (int mt = 0; mt < 4; mt++) {
            float p0 = 0.f, p1 = 0.f;
            #pragma unroll
            for (int nt = 0; nt < 4; nt++) {
                p0 += acc[mt][nt][0] * acc[mt][nt][0] + acc[mt][nt][1] * acc[mt][nt][1];
                p1 += acc[mt][nt][2] * acc[mt][nt][2] + acc[mt][nt][3] * acc[mt][nt][3];
            }
            int rl = wm + mt * 16 + (l >> 2);
            sq[rl * 16 + hl * 8 + slot] = p0;
            sq[(rl + 8) * 16 + hl * 8 + slot] = p1;
        }
        __syncthreads();

        bf16* dst = (z == 1) ? b_Qn : b_Kn;
        const int hg = (col0 >> 6) + hl;
        #pragma unroll
        for (int mt = 0; mt < 4; mt++) {
            int rl = wm + mt * 16 + (l >> 2);
            float ss0 = 0.f, ss1 = 0.f;
            #pragma unroll
            for (int s = 0; s < 8; s++) {
                ss0 += sq[rl * 16 + hl * 8 + s];
                ss1 += sq[(rl + 8) * 16 + hl * 8 + s];
            }
            float inv0 = 1.0f / (sqrtf(ss0) + EPSN);
            float inv1 = 1.0f / (sqrtf(ss1) + EPSN);
            #pragma unroll
            for (int nt = 0; nt < 4; nt++) {
                int d = (wn & 63) + nt * 8 + (l & 3) * 2;
                ((uint32_t*)dst)[((size_t)hg * S_LEN + row0 + rl) * 32 + (d >> 1)] =
                    packbf(acc[mt][nt][0] * inv0, acc[mt][nt][1] * inv0);
                ((uint32_t*)dst)[((size_t)hg * S_LEN + row0 + rl + 8) * 32 + (d >> 1)] =
                    packbf(acc[mt][nt][2] * inv1, acc[mt][nt][3] * inv1);
            }
        }
    } else {
        // transpose, emit v_Vt (single fp16) [h][d][s]
        __half* sh = (__half*)sm_;
        #pragma unroll
        for (int mt = 0; mt < 4; mt++) {
            int rl = wm + mt * 16 + (l >> 2);
            #pragma unroll
            for (int nt = 0; nt < 4; nt++) {
                int c0 = wn + nt * 8 + (l & 3) * 2;
                #pragma unroll
                for (int j = 0; j < 2; j++) {
                    sh[(c0 + j) * 136 + rl]     = __float2half(acc[mt][nt][j]);
                    sh[(c0 + j) * 136 + rl + 8] = __float2half(acc[mt][nt][2 + j]);
                }
            }
        }
        __syncthreads();
        int cl = tid >> 1, soff = (tid & 1) * 64;
        int hg = (col0 + cl) >> 6, d = (col0 + cl) & 63;
        size_t gbase = ((size_t)hg * DK + d) * S_LEN + row0 + soff;
        const uint4* srch = (const uint4*)(sh + cl * 136 + soff);
        uint4* gh = (uint4*)(v_Vt + gbase);
        #pragma unroll
        for (int i = 0; i < 8; i++) gh[i] = srch[i];
    }
}

// ---------------- out GEMM: 128x64 tiles, 1-term fp16, 4-stage, 3 CTAs/SM ----------------
#define OSTG (128 * 40 + 32 * 72)    // elems/stage: A + B = 7424

__global__ void __launch_bounds__(256, 3)
out_gemm(float* __restrict__ out)
{
    extern __shared__ __half smh_[];

    const int tid = threadIdx.x;
    const int w = tid >> 5, l = tid & 31;
    const int wm = (w & 3) * 32, wn = (w >> 2) * 32;     // 4 M-warps x 2 N-warps
    const int row0 = blockIdx.y * 128, col0 = blockIdx.x * 64;
    const int NT = DM / 32;

    auto issue = [&](int it, int stg) {
        __half* dA = smh_ + stg * OSTG;
        __half* dB = dA + 128 * 40;
        int k0 = it * 32;
        #pragma unroll
        for (int i = 0; i < 2; i++) {
            int pos = tid + i * 256;
            int r = pos >> 2, c = (pos & 3) * 8;
            cp16(dA + r * 40 + c, v_att + (size_t)(row0 + r) * DM + k0 + c);
        }
        {
            int r = tid >> 3, c = (tid & 7) * 8;
            cp16(dB + r * 72 + c, h_Wo + (size_t)(k0 + r) * DM + col0 + c);
        }
        cp_commit();
    };

    float acc[2][4][4];
    #pragma unroll
    for (int a = 0; a < 2; a++)
        #pragma unroll
        for (int b = 0; b < 4; b++)
            #pragma unroll
            for (int c = 0; c < 4; c++) acc[a][b][c] = 0.f;

    issue(0, 0);
    issue(1, 1);
    issue(2, 2);

    for (int it = 0; it < NT; it++) {
        if (it + 3 < NT) cp_wait<2>(); else cp_wait<0>();
        __syncthreads();
        if (it + 3 < NT) issue(it + 3, (it + 3) & 3);

        __half* sA = smh_ + (it & 3) * OSTG;
        __half* sB = sA + 128 * 40;

        #pragma unroll
        for (int kc = 0; kc < 2; kc++) {
            uint32_t af[2][4], bh[2][4];
            #pragma unroll
            for (int mt = 0; mt < 2; mt++)
                ldm4(af[mt][0], af[mt][1], af[mt][2], af[mt][3],
                     cvta_s(sA + (wm + mt * 16 + (l & 15)) * 40 + kc * 16 + ((l >> 4) * 8)));
            #pragma unroll
            for (int np = 0; np < 2; np++)
                ldm4t(bh[np][0], bh[np][1], bh[np][2], bh[np][3],
                      cvta_s(sB + (kc * 16 + (l & 15)) * 72 + wn + np * 16 + ((l >> 4) * 8)));
            #pragma unroll
            for (int mt = 0; mt < 2; mt++)
                #pragma unroll
                for (int nt = 0; nt < 4; nt++)
                    mma_hf(acc[mt][nt], af[mt],
                           bh[nt >> 1][(nt & 1) * 2], bh[nt >> 1][(nt & 1) * 2 + 1]);
        }
    }

    #pragma unroll
    for (int mt = 0; mt < 2; mt++) {
        int r = row0 + wm + mt * 16 + (l >> 2);
        #pragma unroll
        for (int nt = 0; nt < 4; nt++) {
            int c = col0 + wn + nt * 8 + (l & 3) * 2;
            *(float2*)&out[(size_t)r * DM + c] =
                make_float2(acc[mt][nt][0], acc[mt][nt][1]);
            *(float2*)&out[(size_t)(r + 8) * DM + c] =
                make_float2(acc[mt][nt][2], acc[mt][nt][3]);
        }
    }
}

// ---------------- fused attention: q-block 128, 256 thr, 4-stage, safe drain ----------------
#define ASTG (2 * 64 * 72)   // per-stage elems (K bf16 + V f16) = 9216

__global__ void __launch_bounds__(256, 2) attn_mma(const float* __restrict__ bias)
{
    extern __shared__ bf16 sm_[];

    const int tid = threadIdx.x, w = tid >> 5, l = tid & 31;
    const int h = blockIdx.y, qb = blockIdx.x * 128;

    // stage Q tile (128x64) through stage-0/1 area, grab fragments
    #pragma unroll
    for (int i = 0; i < 4; i++) {
        int pos = tid + i * 256;
        int r = pos >> 3, c = (pos & 7) * 8;
        *(uint4*)(sm_ + r * 72 + c) =
            *(const uint4*)(b_Qn + ((size_t)h * S_LEN + qb + r) * DK + c);
    }
    __syncthreads();
    uint32_t qf[4][4];
    #pragma unroll
    for (int dc = 0; dc < 4; dc++)
        ldm4(qf[dc][0], qf[dc][1], qf[dc][2], qf[dc][3],
             cvta_s(sm_ + (w * 16 + (l & 15)) * 72 + dc * 16 + ((l >> 4) * 8)));
    __syncthreads();

    auto issue = [&](int it, int stg) {
        bf16*   dK = sm_ + stg * ASTG;
        __half* dV = (__half*)(dK + 64 * 72);
        int kb = it * 64;
        #pragma unroll
        for (int i = 0; i < 2; i++) {
            int pos = tid + i * 256;
            int r = pos >> 3, c = (pos & 7) * 8;
            cp16(dK + r * 72 + c, b_Kn + ((size_t)h * S_LEN + kb + r) * DK + c);
            cp16(dV + r * 72 + c, v_Vt + ((size_t)h * DK + r) * S_LEN + kb + c);
        }
        cp_commit();
    };

    float oacc[8][4];
    #pragma unroll
    for (int a = 0; a < 8; a++)
        #pragma unroll
        for (int b = 0; b < 4; b++) oacc[a][b] = 0.f;
    float rs_lo = 0.f, rs_hi = 0.f;

    const float* bp = bias + ((size_t)h * S_LEN + qb + w * 16 + (l >> 2)) * S_LEN + (l & 3) * 2;

    issue(0, 0);
    issue(1, 1);
    issue(2, 2);

    const int NT = S_LEN / 64;
    for (int it = 0; it < NT; it++) {
        const int kb = it * 64;
        if (it + 3 < NT) cp_wait<2>(); else cp_wait<0>();
        __syncthreads();
        if (it + 3 < NT) issue(it + 3, (it + 3) & 3);

        bf16*   sK = sm_ + (it & 3) * ASTG;
        __half* sV = (__half*)(sK + 64 * 72);

        // prefetch bias for this tile (hides under the S mma below)
        float2 bv0[8], bv1[8];
        #pragma unroll
        for (int nt = 0; nt < 8; nt++) {
            bv0[nt] = *(const float2*)(bp + kb + nt * 8);
            bv1[nt] = *(const float2*)(bp + kb + nt * 8 + 8 * S_LEN);
        }

        // S = Q @ K^T (128 x 64 tile per block, 16 x 64 per warp)
        float s[8][4];
        #pragma unroll
        for (int a = 0; a < 8; a++)
            #pragma unroll
            for (int b = 0; b < 4; b++) s[a][b] = 0.f;
        #pragma unroll
        for (int dc = 0; dc < 4; dc++) {
            #pragma unroll
            for (int np = 0; np < 4; np++) {
                uint32_t r0, r1, r2, r3;
                ldm4(r0, r1, r2, r3,
                     cvta_s(sK + (np * 16 + (l & 15)) * 72 + dc * 16 + ((l >> 4) * 8)));
                mma_bf(s[2 * np],     qf[dc], r0, r2);
                mma_bf(s[2 * np + 1], qf[dc], r1, r3);
            }
        }

        // p = exp(s*SCALE + bias); row sums
        #pragma unroll
        for (int nt = 0; nt < 8; nt++) {
            float p0 = __expf(fmaf(s[nt][0], SCALE, bv0[nt].x));
            float p1 = __expf(fmaf(s[nt][1], SCALE, bv0[nt].y));
            float p2 = __expf(fmaf(s[nt][2], SCALE, bv1[nt].x));
            float p3 = __expf(fmaf(s[nt][3], SCALE, bv1[nt].y));
            rs_lo += p0 + p1;  rs_hi += p2 + p3;
            s[nt][0] = p0; s[nt][1] = p1; s[nt][2] = p2; s[nt][3] = p3;
        }

        // O += P @ V  (single fp16 each)
        #pragma unroll
        for (int kt = 0; kt < 4; kt++) {
            uint32_t a[4];
            a[0] = packhf(s[2 * kt][0],     s[2 * kt][1]);
            a[1] = packhf(s[2 * kt][2],     s[2 * kt][3]);
            a[2] = packhf(s[2 * kt + 1][0], s[2 * kt + 1][1]);
            a[3] = packhf(s[2 * kt + 1][2], s[2 * kt + 1][3]);
            #pragma unroll
            for (int dp = 0; dp < 4; dp++) {
                uint32_t v0, v1, v2, v3;
                ldm4(v0, v1, v2, v3,
                     cvta_s(sV + (dp * 16 + (l & 15)) * 72 + kt * 16 + ((l >> 4) * 8)));
                mma_hf(oacc[2 * dp],     a, v0, v2);
                mma_hf(oacc[2 * dp + 1], a, v1, v3);
            }
        }
    }

    // finalize: quad-reduce row sums, normalize, emit fp16 att
    rs_lo += __shfl_xor_sync(0xffffffffu, rs_lo, 1);
    rs_lo += __shfl_xor_sync(0xffffffffu, rs_lo, 2);
    rs_hi += __shfl_xor_sync(0xffffffffu, rs_hi, 1);
    rs_hi += __shfl_xor_sync(0xffffffffu, rs_hi, 2);
    float il = 1.0f / rs_lo, ih = 1.0f / rs_hi;

    #pragma unroll
    for (int nt = 0; nt < 8; nt++) {
        int r = qb + w * 16 + (l >> 2);
        int c = h * DK + nt * 8 + (l & 3) * 2;
        size_t i0 = ((size_t)r * DM + c) >> 1;
        size_t i1 = ((size_t)(r + 8) * DM + c) >> 1;
        ((uint32_t*)v_att)[i0] = packhf(oacc[nt][0] * il, oacc[nt][1] * il);
        ((uint32_t*)v_att)[i1] = packhf(oacc[nt][2] * ih, oacc[nt][3] * ih);
    }
}

// ---------------- launcher ----------------
extern "C" void kernel_launch(void* const* d_in, const int* in_sizes, int n_in,
                              void* d_out, int out_size)
{
    (void)in_sizes; (void)n_in; (void)out_size;
    const float* Qin  = (const float*)d_in[0];
    const float* Kin  = (const float*)d_in[1];
    const float* Vin  = (const float*)d_in[2];
    const float* bias = (const float*)d_in[3];
    const float* Wq   = (const float*)d_in[4];
    const float* Wk   = (const float*)d_in[5];
    const float* Wv   = (const float*)d_in[6];
    const float* Wo   = (const float*)d_in[7];
    float* out = (float*)d_out;

    const int NPREP = 3 * (S_LEN * DM / 4) + 4 * (DM * DM / 4);
    prep_all<<<NPREP / 256, 256>>>((const float4*)Qin, (const float4*)Kin,
                                   (const float4*)Vin, (const float4*)Wq,
                                   (const float4*)Wk, (const float4*)Wv,
                                   (const float4*)Wo);

    // fused QKV projections: uniform 1-term, z=0 V, z=1 Q, z=2 K
    const int smemG = 3 * GSTG * 2;                        // 56832 B
    cudaFuncSetAttribute(qkv_gemm,
                         cudaFuncAttributeMaxDynamicSharedMemorySize, smemG);
    qkv_gemm<<<dim3(DM / 128, S_LEN / 128, 3), 256, smemG>>>();

    const int smemA = 4 * ASTG * 2;                        // 73728 B
    cudaFuncSetAttribute(attn_mma,
                         cudaFuncAttributeMaxDynamicSharedMemorySize, smemA);
    attn_mma<<<dim3(S_LEN / 128, NH), 256, smemA>>>(bias);

    const int smemO = 4 * OSTG * 2;                        // 59392 B
    cudaFuncSetAttribute(out_gemm,
                         cudaFuncAttributeMaxDynamicSharedMemorySize, smemO);
    out_gemm<<<dim3(DM / 64, S_LEN / 128), 256, smemO>>>(out);
}

// round 16
// speedup vs baseline: 1.2437x; 1.0428x over previous
#include <cuda_runtime.h>
#include <cuda_bf16.h>
#include <cuda_fp16.h>
#include <math.h>
#include <stdint.h>

#define S_LEN 2048
#define DM    1024
#define NH    16
#define DK    64
#define SCALE 0.125f
#define EPSN  1e-6f

typedef __nv_bfloat16 bf16;

// ---------------- scratch (__device__ globals; allocation-free) ----------------
__device__ bf16   b_Qin[(size_t)S_LEN * DM];
__device__ bf16   b_Kin[(size_t)S_LEN * DM];
__device__ __half h_Vin[(size_t)S_LEN * DM];       // V input, single fp16
__device__ bf16   b_Wq[(size_t)DM * DM];
__device__ bf16   b_Wk[(size_t)DM * DM];
__device__ __half h_Wv[(size_t)DM * DM];           // W_v single fp16
__device__ __half h_Wo[(size_t)DM * DM];           // W_o single fp16

__device__ bf16   b_Qn[(size_t)NH * S_LEN * DK];   // normalized Q, [h][s][64]
__device__ bf16   b_Kn[(size_t)NH * S_LEN * DK];
__device__ __half v_Vt[(size_t)NH * DK * S_LEN];   // V^T fp16, [h][64][2048]

__device__ __half v_att[(size_t)S_LEN * DM];       // attended, single fp16

// ---------------- helpers ----------------
__device__ __forceinline__ uint32_t cvta_s(const void* p) {
    return (uint32_t)__cvta_generic_to_shared(p);
}
__device__ __forceinline__ void cp16(void* s, const void* g) {
    asm volatile("cp.async.cg.shared.global [%0],[%1],16;" ::
                 "r"(cvta_s(s)), "l"(g));
}
__device__ __forceinline__ void cp_commit() {
    asm volatile("cp.async.commit_group;");
}
template<int N>
__device__ __forceinline__ void cp_wait() {
    asm volatile("cp.async.wait_group %0;" :: "n"(N));
}
__device__ __forceinline__ void ldm4(uint32_t& r0, uint32_t& r1, uint32_t& r2, uint32_t& r3,
                                     uint32_t a) {
    asm volatile("ldmatrix.sync.aligned.m8n8.x4.shared.b16 {%0,%1,%2,%3},[%4];"
                 : "=r"(r0), "=r"(r1), "=r"(r2), "=r"(r3) : "r"(a));
}
__device__ __forceinline__ void ldm4t(uint32_t& r0, uint32_t& r1, uint32_t& r2, uint32_t& r3,
                                      uint32_t a) {
    asm volatile("ldmatrix.sync.aligned.m8n8.x4.trans.shared.b16 {%0,%1,%2,%3},[%4];"
                 : "=r"(r0), "=r"(r1), "=r"(r2), "=r"(r3) : "r"(a));
}
__device__ __forceinline__ void mma_bf(float c[4], const uint32_t a[4],
                                       uint32_t b0, uint32_t b1) {
    asm volatile(
        "mma.sync.aligned.m16n8k16.row.col.f32.bf16.bf16.f32 "
        "{%0,%1,%2,%3},{%4,%5,%6,%7},{%8,%9},{%0,%1,%2,%3};"
        : "+f"(c[0]), "+f"(c[1]), "+f"(c[2]), "+f"(c[3])
        : "r"(a[0]), "r"(a[1]), "r"(a[2]), "r"(a[3]), "r"(b0), "r"(b1));
}
__device__ __forceinline__ void mma_hf(float c[4], const uint32_t a[4],
                                       uint32_t b0, uint32_t b1) {
    asm volatile(
        "mma.sync.aligned.m16n8k16.row.col.f32.f16.f16.f32 "
        "{%0,%1,%2,%3},{%4,%5,%6,%7},{%8,%9},{%0,%1,%2,%3};"
        : "+f"(c[0]), "+f"(c[1]), "+f"(c[2]), "+f"(c[3])
        : "r"(a[0]), "r"(a[1]), "r"(a[2]), "r"(a[3]), "r"(b0), "r"(b1));
}
// pack two fp32 -> bf16x2 / f16x2; first arg in low 16 bits
__device__ __forceinline__ uint32_t packbf(float lo, float hi) {
    uint32_t r;
    asm("cvt.rn.bf16x2.f32 %0,%1,%2;" : "=r"(r) : "f"(hi), "f"(lo));
    return r;
}
__device__ __forceinline__ uint32_t packhf(float lo, float hi) {
    uint32_t r;
    asm("cvt.rn.f16x2.f32 %0,%1,%2;" : "=r"(r) : "f"(hi), "f"(lo));
    return r;
}

// ---------------- fused conversions (one launch) ----------------
__device__ __forceinline__ void cvt1(const float4* x, uint32_t* y, int i) {
    float4 v = x[i];
    y[2 * i + 0] = packbf(v.x, v.y);
    y[2 * i + 1] = packbf(v.z, v.w);
}
__device__ __forceinline__ void cvt1h(const float4* x, uint32_t* y, int i) {
    float4 v = x[i];
    y[2 * i + 0] = packhf(v.x, v.y);
    y[2 * i + 1] = packhf(v.z, v.w);
}
__global__ void prep_all(const float4* Qin, const float4* Kin, const float4* Vin,
                         const float4* Wq, const float4* Wk, const float4* Wv,
                         const float4* Wo)
{
    const int NI = S_LEN * DM / 4;
    const int NW = DM * DM / 4;
    int i = blockIdx.x * 256 + threadIdx.x;
    if (i < NI) { cvt1(Qin, (uint32_t*)b_Qin, i); return; }
    i -= NI;
    if (i < NI) { cvt1(Kin, (uint32_t*)b_Kin, i); return; }
    i -= NI;
    if (i < NI) { cvt1h(Vin, (uint32_t*)h_Vin, i); return; }
    i -= NI;
    if (i < NW) { cvt1(Wq, (uint32_t*)b_Wq, i); return; }
    i -= NW;
    if (i < NW) { cvt1(Wk, (uint32_t*)b_Wk, i); return; }
    i -= NW;
    if (i < NW) { cvt1h(Wv, (uint32_t*)h_Wv, i); return; }
    i -= NW;
    cvt1h(Wo, (uint32_t*)h_Wo, i);
}

// ---------------- fused QKV projection GEMM (uniform 1-term, z selects role) ----------------
#define GSTG (128 * 40 + 32 * 136)   // elems/stage: A + B = 9472

__global__ void __launch_bounds__(256, 2)
qkv_gemm()
{
    extern __shared__ bf16 sm_[];
    const int z = blockIdx.z;
    const bool vrole = (z == 0);
    const char* Ap = vrole ? (const char*)h_Vin : (z == 1) ? (const char*)b_Qin
                                                           : (const char*)b_Kin;
    const char* Bp = vrole ? (const char*)h_Wv : (z == 1) ? (const char*)b_Wq
                                                          : (const char*)b_Wk;

    const int tid = threadIdx.x;
    const int w = tid >> 5, l = tid & 31;
    const int wm = (w >> 2) * 64, wn = (w & 3) * 32;
    const int row0 = blockIdx.y * 128, col0 = blockIdx.x * 128;
    const int NT = DM / 32;

    auto issue = [&](int it, int stg) {
        bf16* dA = sm_ + stg * GSTG;
        bf16* dB = dA + 128 * 40;
        int k0 = it * 32;
        #pragma unroll
        for (int i = 0; i < 2; i++) {
            int pos = tid + i * 256;
            int r = pos >> 2, c = (pos & 3) * 8;
            cp16(dA + r * 40 + c, Ap + ((size_t)(row0 + r) * DM + k0 + c) * 2);
        }
        #pragma unroll
        for (int i = 0; i < 2; i++) {
            int pos = tid + i * 256;
            int r = pos >> 4, c = (pos & 15) * 8;
            cp16(dB + r * 136 + c, Bp + ((size_t)(k0 + r) * DM + col0 + c) * 2);
        }
        cp_commit();
    };

    float acc[4][4][4];
    #pragma unroll
    for (int a = 0; a < 4; a++)
        #pragma unroll
        for (int b = 0; b < 4; b++)
            #pragma unroll
            for (int c = 0; c < 4; c++) acc[a][b][c] = 0.f;

    issue(0, 0);
    issue(1, 1);

    for (int it = 0; it < NT; it++) {
        if (it + 2 < NT) cp_wait<1>(); else cp_wait<0>();
        __syncthreads();
        if (it + 2 < NT) issue(it + 2, (it + 2) % 3);

        bf16* sA = sm_ + (it % 3) * GSTG;
        bf16* sB = sA + 128 * 40;

        #pragma unroll
        for (int kc = 0; kc < 2; kc++) {
            uint32_t af[4][4], bfh[2][4];
            #pragma unroll
            for (int mt = 0; mt < 4; mt++)
                ldm4(af[mt][0], af[mt][1], af[mt][2], af[mt][3],
                     cvta_s(sA + (wm + mt * 16 + (l & 15)) * 40 + kc * 16 + ((l >> 4) * 8)));
            #pragma unroll
            for (int np = 0; np < 2; np++)
                ldm4t(bfh[np][0], bfh[np][1], bfh[np][2], bfh[np][3],
                      cvta_s(sB + (kc * 16 + (l & 15)) * 136 + wn + np * 16 + ((l >> 4) * 8)));
            if (!vrole) {
                #pragma unroll
                for (int mt = 0; mt < 4; mt++)
                    #pragma unroll
                    for (int nt = 0; nt < 4; nt++)
                        mma_bf(acc[mt][nt], af[mt],
                               bfh[nt >> 1][(nt & 1) * 2], bfh[nt >> 1][(nt & 1) * 2 + 1]);
            } else {
                #pragma unroll
                for (int mt = 0; mt < 4; mt++)
                    #pragma unroll
                    for (int nt = 0; nt < 4; nt++)
                        mma_hf(acc[mt][nt], af[mt],
                               bfh[nt >> 1][(nt & 1) * 2], bfh[nt >> 1][(nt & 1) * 2 + 1]);
            }
        }
    }
    __syncthreads();   // protect smem reuse in epilogues

    if (!vrole) {
        float* sq = (float*)sm_;                 // 128 rows x 16 (2 heads x 8 partials)
        const int cw = w & 3;
        const int hl = cw >> 1;
        const int slot = (cw & 1) * 4 + (l & 3);
        #pragma unroll
        for (int mt = 0; mt < 4; mt++) {
            float p0 = 0.f, p1 = 0.f;
            #pragma unroll
            for (int nt = 0; nt < 4; nt++) {
                p0 += acc[mt][nt][0] * acc[mt][nt][0] + acc[mt][nt][1] * acc[mt][nt][1];
                p1 += acc[mt][nt][2] * acc[mt][nt][2] + acc[mt][nt][3] * acc[mt][nt][3];
            }
            int rl = wm + mt * 16 + (l >> 2);
            sq[rl * 16 + hl * 8 + slot] = p0;
            sq[(rl + 8) * 16 + hl * 8 + slot] = p1;
        }
        __syncthreads();

        bf16* dst = (z == 1) ? b_Qn : b_Kn;
        const int hg = (col0 >> 6) + hl;
        #pragma unroll
        for (int mt = 0; mt < 4; mt++) {
            int rl = wm + mt * 16 + (l >> 2);
            float ss0 = 0.f, ss1 = 0.f;
            #pragma unroll
            for (int s = 0; s < 8; s++) {
                ss0 += sq[rl * 16 + hl * 8 + s];
                ss1 += sq[(rl + 8) * 16 + hl * 8 + s];
            }
            float inv0 = 1.0f / (sqrtf(ss0) + EPSN);
            float inv1 = 1.0f / (sqrtf(ss1) + EPSN);
            #pragma unroll
            for (int nt = 0; nt < 4; nt++) {
                int d = (wn & 63) + nt * 8 + (l & 3) * 2;
                ((uint32_t*)dst)[((size_t)hg * S_LEN + row0 + rl) * 32 + (d >> 1)] =
                    packbf(acc[mt][nt][0] * inv0, acc[mt][nt][1] * inv0);
                ((uint32_t*)dst)[((size_t)hg * S_LEN + row0 + rl + 8) * 32 + (d >> 1)] =
                    packbf(acc[mt][nt][2] * inv1, acc[mt][nt][3] * inv1);
            }
        }
    } else {
        __half* sh = (__half*)sm_;
        #pragma unroll
        for (int mt = 0; mt < 4; mt++) {
            int rl = wm + mt * 16 + (l >> 2);
            #pragma unroll
            for (int nt = 0; nt < 4; nt++) {
                int c0 = wn + nt * 8 + (l & 3) * 2;
                #pragma unroll
                for (int j = 0; j < 2; j++) {
                    sh[(c0 + j) * 136 + rl]     = __float2half(acc[mt][nt][j]);
                    sh[(c0 + j) * 136 + rl + 8] = __float2half(acc[mt][nt][2 + j]);
                }
            }
        }
        __syncthreads();
        int cl = tid >> 1, soff = (tid & 1) * 64;
        int hg = (col0 + cl) >> 6, d = (col0 + cl) & 63;
        size_t gbase = ((size_t)hg * DK + d) * S_LEN + row0 + soff;
        const uint4* srch = (const uint4*)(sh + cl * 136 + soff);
        uint4* gh = (uint4*)(v_Vt + gbase);
        #pragma unroll
        for (int i = 0; i < 8; i++) gh[i] = srch[i];
    }
}

// ---------------- out GEMM: 64x64 tiles (grid 512), 1-term fp16, 4-stage ----------------
#define OSTG (64 * 40 + 32 * 72)    // f16 elems/stage: A + B = 4864

__global__ void __launch_bounds__(256, 3)
out_gemm(float* __restrict__ out)
{
    extern __shared__ __half smh_[];

    const int tid = threadIdx.x;
    const int w = tid >> 5, l = tid & 31;
    const int wm = (w & 3) * 16, wn = (w >> 2) * 32;     // 4 M-warps x 2 N-warps
    const int row0 = blockIdx.y * 64, col0 = blockIdx.x * 64;
    const int NT = DM / 32;

    auto issue = [&](int it, int stg) {
        __half* dA = smh_ + stg * OSTG;
        __half* dB = dA + 64 * 40;
        int k0 = it * 32;
        {   // A: 64 rows x 32 f16 = 256 cp16, 1/thread
            int r = tid >> 2, c = (tid & 3) * 8;
            cp16(dA + r * 40 + c, v_att + (size_t)(row0 + r) * DM + k0 + c);
        }
        {   // B: 32 rows x 64 f16 = 256 cp16, 1/thread
            int r = tid >> 3, c = (tid & 7) * 8;
            cp16(dB + r * 72 + c, h_Wo + (size_t)(k0 + r) * DM + col0 + c);
        }
        cp_commit();
    };

    float acc[4][4];
    #pragma unroll
    for (int b = 0; b < 4; b++)
        #pragma unroll
        for (int c = 0; c < 4; c++) acc[b][c] = 0.f;

    issue(0, 0);
    issue(1, 1);
    issue(2, 2);

    for (int it = 0; it < NT; it++) {
        if (it + 3 < NT) cp_wait<2>(); else cp_wait<0>();
        __syncthreads();
        if (it + 3 < NT) issue(it + 3, (it + 3) & 3);

        __half* sA = smh_ + (it & 3) * OSTG;
        __half* sB = sA + 64 * 40;

        #pragma unroll
        for (int kc = 0; kc < 2; kc++) {
            uint32_t af[4], bh[2][4];
            ldm4(af[0], af[1], af[2], af[3],
                 cvta_s(sA + (wm + (l & 15)) * 40 + kc * 16 + ((l >> 4) * 8)));
            #pragma unroll
            for (int np = 0; np < 2; np++)
                ldm4t(bh[np][0], bh[np][1], bh[np][2], bh[np][3],
                      cvta_s(sB + (kc * 16 + (l & 15)) * 72 + wn + np * 16 + ((l >> 4) * 8)));
            #pragma unroll
            for (int nt = 0; nt < 4; nt++)
                mma_hf(acc[nt], af,
                       bh[nt >> 1][(nt & 1) * 2], bh[nt >> 1][(nt & 1) * 2 + 1]);
        }
    }

    int r = row0 + wm + (l >> 2);
    #pragma unroll
    for (int nt = 0; nt < 4; nt++) {
        int c = col0 + wn + nt * 8 + (l & 3) * 2;
        *(float2*)&out[(size_t)r * DM + c] = make_float2(acc[nt][0], acc[nt][1]);
        *(float2*)&out[(size_t)(r + 8) * DM + c] = make_float2(acc[nt][2], acc[nt][3]);
    }
}

// ---------------- fused attention: bias via cp.async smem, 2-stage, 2 sync/tile ----------------
// Stage layout: K 64x72 bf16 (9216 B) | V 64x72 f16 (9216 B) | bias 128x72 f32 (36864 B)
#define ASTG_E 27648   // stage size in bf16 elems (55296 B / 2)

__global__ void __launch_bounds__(256, 2) attn_mma(const float* __restrict__ bias)
{
    extern __shared__ bf16 sm_[];

    const int tid = threadIdx.x, w = tid >> 5, l = tid & 31;
    const int h = blockIdx.y, qb = blockIdx.x * 128;

    // stage Q tile (128x64) through stage-0 K+V area (18432 B), grab fragments
    #pragma unroll
    for (int i = 0; i < 4; i++) {
        int pos = tid + i * 256;
        int r = pos >> 3, c = (pos & 7) * 8;
        *(uint4*)(sm_ + r * 72 + c) =
            *(const uint4*)(b_Qn + ((size_t)h * S_LEN + qb + r) * DK + c);
    }
    __syncthreads();
    uint32_t qf[4][4];
    #pragma unroll
    for (int dc = 0; dc < 4; dc++)
        ldm4(qf[dc][0], qf[dc][1], qf[dc][2], qf[dc][3],
             cvta_s(sm_ + (w * 16 + (l & 15)) * 72 + dc * 16 + ((l >> 4) * 8)));
    __syncthreads();

    auto issue = [&](int it, int stg) {
        bf16*   dK = sm_ + stg * ASTG_E;
        __half* dV = (__half*)(dK + 64 * 72);
        float*  dB = (float*)(dV + 64 * 72);
        int kb = it * 64;
        #pragma unroll
        for (int i = 0; i < 2; i++) {
            int pos = tid + i * 256;
            int r = pos >> 3, c = (pos & 7) * 8;
            cp16(dK + r * 72 + c, b_Kn + ((size_t)h * S_LEN + kb + r) * DK + c);
            cp16(dV + r * 72 + c, v_Vt + ((size_t)h * DK + r) * S_LEN + kb + c);
        }
        // bias: 128 rows x 64 floats = 2048 cp16 (8 per thread)
        #pragma unroll
        for (int i = 0; i < 8; i++) {
            int pos = tid + i * 256;
            int r = pos >> 4, c4 = (pos & 15) * 4;
            cp16(dB + r * 72 + c4,
                 bias + ((size_t)h * S_LEN + qb + r) * S_LEN + kb + c4);
        }
        cp_commit();
    };

    float oacc[8][4];
    #pragma unroll
    for (int a = 0; a < 8; a++)
        #pragma unroll
        for (int b = 0; b < 4; b++) oacc[a][b] = 0.f;
    float rs_lo = 0.f, rs_hi = 0.f;

    issue(0, 0);

    const int NT = S_LEN / 64;
    const int brow = w * 16 + (l >> 2);
    const int bcol = (l & 3) * 2;

    for (int it = 0; it < NT; it++) {
        if (it + 1 < NT) { issue(it + 1, (it + 1) & 1); cp_wait<1>(); }
        else             { cp_wait<0>(); }
        __syncthreads();

        bf16*   sK = sm_ + (it & 1) * ASTG_E;
        __half* sV = (__half*)(sK + 64 * 72);
        float*  sB = (float*)(sV + 64 * 72);

        // S = Q @ K^T (128 x 64 tile per block, 16 x 64 per warp)
        float s[8][4];
        #pragma unroll
        for (int a = 0; a < 8; a++)
            #pragma unroll
            for (int b = 0; b < 4; b++) s[a][b] = 0.f;
        #pragma unroll
        for (int dc = 0; dc < 4; dc++) {
            #pragma unroll
            for (int np = 0; np < 4; np++) {
                uint32_t r0, r1, r2, r3;
                ldm4(r0, r1, r2, r3,
                     cvta_s(sK + (np * 16 + (l & 15)) * 72 + dc * 16 + ((l >> 4) * 8)));
                mma_bf(s[2 * np],     qf[dc], r0, r2);
                mma_bf(s[2 * np + 1], qf[dc], r1, r3);
            }
        }

        // p = exp(s*SCALE + bias[smem]); row sums
        #pragma unroll
        for (int nt = 0; nt < 8; nt++) {
            float2 b0 = *(float2*)(sB + brow * 72 + nt * 8 + bcol);
            float2 b1 = *(float2*)(sB + (brow + 8) * 72 + nt * 8 + bcol);
            float p0 = __expf(fmaf(s[nt][0], SCALE, b0.x));
            float p1 = __expf(fmaf(s[nt][1], SCALE, b0.y));
            float p2 = __expf(fmaf(s[nt][2], SCALE, b1.x));
            float p3 = __expf(fmaf(s[nt][3], SCALE, b1.y));
            rs_lo += p0 + p1;  rs_hi += p2 + p3;
            s[nt][0] = p0; s[nt][1] = p1; s[nt][2] = p2; s[nt][3] = p3;
        }

        // O += P @ V  (single fp16 each)
        #pragma unroll
        for (int kt = 0; kt < 4; kt++) {
            uint32_t a[4];
            a[0] = packhf(s[2 * kt][0],     s[2 * kt][1]);
            a[1] = packhf(s[2 * kt][2],     s[2 * kt][3]);
            a[2] = packhf(s[2 * kt + 1][0], s[2 * kt + 1][1]);
            a[3] = packhf(s[2 * kt + 1][2], s[2 * kt + 1][3]);
            #pragma unroll
            for (int dp = 0; dp < 4; dp++) {
                uint32_t v0, v1, v2, v3;
                ldm4(v0, v1, v2, v3,
                     cvta_s(sV + (dp * 16 + (l & 15)) * 72 + kt * 16 + ((l >> 4) * 8)));
                mma_hf(oacc[2 * dp],     a, v0, v2);
                mma_hf(oacc[2 * dp + 1], a, v1, v3);
            }
        }
        __syncthreads();   // readers done before next issue overwrites this stage
    }

    // finalize: quad-reduce row sums, normalize, emit fp16 att
    rs_lo += __shfl_xor_sync(0xffffffffu, rs_lo, 1);
    rs_lo += __shfl_xor_sync(0xffffffffu, rs_lo, 2);
    rs_hi += __shfl_xor_sync(0xffffffffu, rs_hi, 1);
    rs_hi += __shfl_xor_sync(0xffffffffu, rs_hi, 2);
    float il = 1.0f / rs_lo, ih = 1.0f / rs_hi;

    #pragma unroll
    for (int nt = 0; nt < 8; nt++) {
        int r = qb + w * 16 + (l >> 2);
        int c = h * DK + nt * 8 + (l & 3) * 2;
        size_t i0 = ((size_t)r * DM + c) >> 1;
        size_t i1 = ((size_t)(r + 8) * DM + c) >> 1;
        ((uint32_t*)v_att)[i0] = packhf(oacc[nt][0] * il, oacc[nt][1] * il);
        ((uint32_t*)v_att)[i1] = packhf(oacc[nt][2] * ih, oacc[nt][3] * ih);
    }
}

// ---------------- launcher ----------------
extern "C" void kernel_launch(void* const* d_in, const int* in_sizes, int n_in,
                              void* d_out, int out_size)
{
    (void)in_sizes; (void)n_in; (void)out_size;
    const float* Qin  = (const float*)d_in[0];
    const float* Kin  = (const float*)d_in[1];
    const float* Vin  = (const float*)d_in[2];
    const float* bias = (const float*)d_in[3];
    const float* Wq   = (const float*)d_in[4];
    const float* Wk   = (const float*)d_in[5];
    const float* Wv   = (const float*)d_in[6];
    const float* Wo   = (const float*)d_in[7];
    float* out = (float*)d_out;

    const int NPREP = 3 * (S_LEN * DM / 4) + 4 * (DM * DM / 4);
    prep_all<<<NPREP / 256, 256>>>((const float4*)Qin, (const float4*)Kin,
                                   (const float4*)Vin, (const float4*)Wq,
                                   (const float4*)Wk, (const float4*)Wv,
                                   (const float4*)Wo);

    // fused QKV projections: uniform 1-term, z=0 V, z=1 Q, z=2 K
    const int smemG = 3 * GSTG * 2;                        // 56832 B
    cudaFuncSetAttribute(qkv_gemm,
                         cudaFuncAttributeMaxDynamicSharedMemorySize, smemG);
    qkv_gemm<<<dim3(DM / 128, S_LEN / 128, 3), 256, smemG>>>();

    const int smemA = 2 * ASTG_E * 2;                      // 110592 B
    cudaFuncSetAttribute(attn_mma,
                         cudaFuncAttributeMaxDynamicSharedMemorySize, smemA);
    attn_mma<<<dim3(S_LEN / 128, NH), 256, smemA>>>(bias);

    const int smemO = 4 * OSTG * 2;                        // 38912 B
    cudaFuncSetAttribute(out_gemm,
                         cudaFuncAttributeMaxDynamicSharedMemorySize, smemO);
    out_gemm<<<dim3(DM / 64, S_LEN / 64), 256, smemO>>>(out);
}